// round 11
// baseline (speedup 1.0000x reference)
#include <cuda_runtime.h>
#include <cuda_fp16.h>
#include <cstddef>
#include <cstdint>

#define H       1024
#define DV      4096
#define DW      512
#define VOCAB   32000
#define NSTEP   39      // MAX_LEN - 1
#define LG_TASKS 2000   // logits tasks per step, 16 rows each
#define LG_A     630    // logits tasks placed in phase A (DRAM balance with fp16 rec)
#define NORM_TASKS 8    // norm-subtract tasks (4000 floats each)

// ---------------- persistent device state (no allocations allowed) ----------------
__device__ float g_h1[2][H];
__device__ float g_c1[H];
__device__ float g_h2[2][H];
__device__ float g_c2[H];
__device__ float g_p2[4 * H];             // lstm2 independent-part partials

__device__ __align__(16) __half g_whh1h[4 * H * H];          // 8 MB
__device__ __align__(16) __half g_wih2h[4 * H * (H + DW)];   // 12.6 MB
__device__ __align__(16) __half g_whh2h[4 * H * H];          // 8 MB

__device__ int   g_wq[VOCAB * (H / 4)];   // int8 w_out cache (packed)
__device__ float g_wscale[VOCAB];

__device__ float g_lmax[2][LG_TASKS];     // per-logits-task lse partials (page = step&1)
__device__ float g_lsum[2][LG_TASKS];
__device__ float g_norm[2];

__device__ unsigned g_cnt[32];            // hierarchical barrier sub-counters
__device__ unsigned g_mst;                // master counter
__device__ unsigned g_gen;                // generation

__device__ __forceinline__ float sigmoidf_(float x) { return 1.0f / (1.0f + expf(-x)); }

__global__ void k_init()
{
    for (int i = 0; i < 32; i++) g_cnt[i] = 0;
    g_mst = 0; g_gen = 0;
}

// ---------------- hierarchical grid barrier (32 | G required) ----------------
__device__ __forceinline__ void gbar(unsigned G)
{
    __syncthreads();
    if (threadIdx.x == 0) {
        __threadfence();
        const unsigned gen = *(volatile unsigned*)&g_gen;
        const unsigned sub = blockIdx.x & 31u;
        const unsigned subTarget = G >> 5;
        if (atomicAdd(&g_cnt[sub], 1u) == subTarget - 1u) {
            atomicExch(&g_cnt[sub], 0u);
            if (atomicAdd(&g_mst, 1u) == 31u) {
                atomicExch(&g_mst, 0u);
                __threadfence();
                atomicAdd(&g_gen, 1u);
            } else {
                while (*(volatile unsigned*)&g_gen == gen) __nanosleep(32);
            }
        } else {
            while (*(volatile unsigned*)&g_gen == gen) __nanosleep(64);
        }
        __threadfence();
    }
    __syncthreads();
}

// ---------------- convert recurrence weights to fp16 (once per launch, stream B) ----------------
__global__ void k_cvt(const float* __restrict__ w_hh1, const float* __restrict__ w_ih2,
                      const float* __restrict__ w_hh2)
{
    const int stride = gridDim.x * blockDim.x;
    const int t0 = blockIdx.x * blockDim.x + threadIdx.x;
    const int n1 = 4 * H * H / 2, n2 = 4 * H * (H + DW) / 2;
    const float2* s1 = (const float2*)w_hh1;  __half2* d1 = (__half2*)g_whh1h;
    const float2* s2 = (const float2*)w_ih2;  __half2* d2 = (__half2*)g_wih2h;
    const float2* s3 = (const float2*)w_hh2;  __half2* d3 = (__half2*)g_whh2h;
    for (int i = t0; i < n1; i += stride) d1[i] = __float22half2_rn(s1[i]);
    for (int i = t0; i < n2; i += stride) d2[i] = __float22half2_rn(s2[i]);
    for (int i = t0; i < n1; i += stride) d3[i] = __float22half2_rn(s3[i]);
}

// ---------------- quantize w_out rows to int8 (once per launch, stream B) ----------------
__global__ void k_quant_w(const float* __restrict__ w)
{
    const int warp = threadIdx.x >> 5;
    const int lane = threadIdx.x & 31;
    const int row0 = blockIdx.x * 32 + warp * 4;

    for (int rr = 0; rr < 4; rr++) {
        const int row = row0 + rr;
        const float4* wr = (const float4*)(w + (size_t)row * H);
        float4 v[8];
        float m = 0.0f;
        #pragma unroll
        for (int i = 0; i < 8; i++) {
            v[i] = wr[lane + 32 * i];
            m = fmaxf(m, fmaxf(fmaxf(fabsf(v[i].x), fabsf(v[i].y)),
                               fmaxf(fabsf(v[i].z), fabsf(v[i].w))));
        }
        #pragma unroll
        for (int o = 16; o; o >>= 1) m = fmaxf(m, __shfl_xor_sync(0xffffffffu, m, o));
        const float inv = (m > 0.0f) ? 127.0f / m : 0.0f;
        #pragma unroll
        for (int i = 0; i < 8; i++) {
            const int a = (int)rintf(v[i].x * inv);
            const int b = (int)rintf(v[i].y * inv);
            const int c = (int)rintf(v[i].z * inv);
            const int d = (int)rintf(v[i].w * inv);
            g_wq[row * (H / 4) + lane + 32 * i] =
                (a & 0xFF) | ((b & 0xFF) << 8) | ((c & 0xFF) << 16) | ((d & 0xFF) << 24);
        }
        if (lane == 0) g_wscale[row] = m / 127.0f;
    }
}

// ---------------- LSTM1 encode (h=c=0, x=vid) -> h1[0], c1  (fp32 weights) ----------------
__global__ void k_lstm1_enc(const float* __restrict__ w_ih, const float* __restrict__ x,
                            const float* __restrict__ b_ih, const float* __restrict__ b_hh)
{
    __shared__ float sx[DV];
    __shared__ float red[4];
    const int j = blockIdx.x, tid = threadIdx.x, warp = tid >> 5, lane = tid & 31;

    for (int i = tid; i < DV; i += 128) sx[i] = x[i];
    __syncthreads();

    const int r = warp * H + j;
    const float4* wr = (const float4*)(w_ih + (size_t)r * DV);
    const float4* xv = (const float4*)sx;
    float s = 0.0f;
    #pragma unroll
    for (int k0 = 0; k0 < DV / 4; k0 += 256) {
        float4 a[8];
        #pragma unroll
        for (int u = 0; u < 8; u++) a[u] = wr[k0 + lane + 32 * u];
        #pragma unroll
        for (int u = 0; u < 8; u++) {
            const float4 b = xv[k0 + lane + 32 * u];
            s += a[u].x * b.x + a[u].y * b.y + a[u].z * b.z + a[u].w * b.w;
        }
    }
    #pragma unroll
    for (int o = 16; o; o >>= 1) s += __shfl_xor_sync(0xffffffffu, s, o);
    if (lane == 0) red[warp] = s + b_ih[r] + b_hh[r];
    __syncthreads();

    if (tid == 0) {
        const float gi = red[0], gf = red[1], gg = red[2], go = red[3];
        const float cn = sigmoidf_(gi) * tanhf(gg);
        g_c1[j]    = cn;
        g_h1[0][j] = sigmoidf_(go) * tanhf(cn);
    }
}

// ---------------- LSTM2 encode: input [h1(enc), zeros], h=c=0 -> h2[0], c2 (fp32) ----------------
__global__ void k_l2enc(const float* __restrict__ w_ih,
                        const float* __restrict__ b_ih, const float* __restrict__ b_hh)
{
    __shared__ float sh[H];
    __shared__ float red[4];
    const int j = blockIdx.x, tid = threadIdx.x, warp = tid >> 5, lane = tid & 31;

    for (int i = tid; i < H; i += 128) sh[i] = g_h1[0][i];
    __syncthreads();

    const int r = warp * H + j;
    const float4* wr = (const float4*)(w_ih + (size_t)r * (H + DW));
    const float4* hv = (const float4*)sh;
    float4 a[8];
    #pragma unroll
    for (int u = 0; u < 8; u++) a[u] = wr[lane + 32 * u];
    float s = 0.0f;
    #pragma unroll
    for (int u = 0; u < 8; u++) {
        const float4 b = hv[lane + 32 * u];
        s += a[u].x * b.x + a[u].y * b.y + a[u].z * b.z + a[u].w * b.w;
    }
    #pragma unroll
    for (int o = 16; o; o >>= 1) s += __shfl_xor_sync(0xffffffffu, s, o);
    if (lane == 0) red[warp] = s + b_ih[r] + b_hh[r];
    __syncthreads();

    if (tid == 0) {
        const float gi = red[0], gf = red[1], gg = red[2], go = red[3];
        const float cn = sigmoidf_(gi) * tanhf(gg);   // c_prev = 0
        g_c2[j]    = cn;
        g_h2[0][j] = sigmoidf_(go) * tanhf(cn);
    }
}

// ---------------- helpers ----------------
__device__ __forceinline__ int pack4(float4 v, float inv)
{
    const int a = (int)rintf(v.x * inv);
    const int b = (int)rintf(v.y * inv);
    const int c = (int)rintf(v.z * inv);
    const int d = (int)rintf(v.w * inv);
    return (a & 0xFF) | ((b & 0xFF) << 8) | ((c & 0xFF) << 16) | ((d & 0xFF) << 24);
}

// dot of 8 fp16 weights (one int4) against 8 fp32 smem values
__device__ __forceinline__ float dot8h(int4 p, const float4* hv4, int pairIdx)
{
    const float4 hA = hv4[pairIdx];
    const float4 hB = hv4[pairIdx + 1];
    const float2 w0 = __half22float2(*(__half2*)&p.x);
    const float2 w1 = __half22float2(*(__half2*)&p.y);
    const float2 w2 = __half22float2(*(__half2*)&p.z);
    const float2 w3 = __half22float2(*(__half2*)&p.w);
    return w0.x * hA.x + w0.y * hA.y + w1.x * hA.z + w1.y * hA.w
         + w2.x * hB.x + w2.y * hB.y + w3.x * hB.z + w3.y * hB.w;
}

// ---------------- the persistent decode kernel ----------------
__global__ void __launch_bounds__(128, 8)
k_decode(const float* __restrict__ b_ih1, const float* __restrict__ b_hh1,
         const float* __restrict__ b_ih2, const float* __restrict__ b_hh2,
         const float* __restrict__ emb,  const float* __restrict__ b_out,
         float* __restrict__ out, unsigned G)
{
    __shared__ float sv[H + DW];      // staging for matvec inputs
    __shared__ int4  qh4[H / 16];     // per-block quantized h2 (persists across phases of a step)
    __shared__ float red[4];
    __shared__ float s_m[128];
    __shared__ int   s_i[128];
    __shared__ float s_a[128];
    __shared__ float s_rows[16];
    __shared__ float s_hscale;
    __shared__ int   s_gidx;

    const unsigned b   = blockIdx.x;
    const int tid  = threadIdx.x;
    const int warp = tid >> 5;
    const int lane = tid & 31;

    // ---------- task bodies ----------
    auto l2ind_task = [&](int j, int pin) {
        const float4* h2p = (const float4*)g_h2[pin];
        for (int k = tid; k < H / 4; k += 128) ((float4*)sv)[k] = __ldcg(h2p + k);
        const float4* ev = (const float4*)(emb + (size_t)s_gidx * DW);
        for (int k = tid; k < DW / 4; k += 128) ((float4*)sv)[H / 4 + k] = ev[k];
        __syncthreads();

        const int r = warp * H + j;
        const int4* whh  = (const int4*)(g_whh2h + (size_t)r * H);
        const int4* wemb = (const int4*)(g_wih2h + (size_t)r * (H + DW) + H);
        const float4* hv = (const float4*)sv;
        int4 a[4], e[2];
        #pragma unroll
        for (int u = 0; u < 4; u++) a[u] = whh[lane + 32 * u];
        #pragma unroll
        for (int u = 0; u < 2; u++) e[u] = wemb[lane + 32 * u];
        float s = 0.0f;
        #pragma unroll
        for (int u = 0; u < 4; u++) s += dot8h(a[u], hv, (lane + 32 * u) * 2);
        #pragma unroll
        for (int u = 0; u < 2; u++) s += dot8h(e[u], hv, H / 4 + (lane + 32 * u) * 2);
        #pragma unroll
        for (int o = 16; o; o >>= 1) s += __shfl_xor_sync(0xffffffffu, s, o);
        if (lane == 0) g_p2[r] = s;
        __syncthreads();
    };

    auto l1_task = [&](int j, int pin, int pout) {
        const float4* h1p = (const float4*)g_h1[pin];
        for (int k = tid; k < H / 4; k += 128) ((float4*)sv)[k] = __ldcg(h1p + k);
        __syncthreads();

        const int r = warp * H + j;
        const int4* wr = (const int4*)(g_whh1h + (size_t)r * H);
        const float4* hv = (const float4*)sv;
        int4 a[4];
        #pragma unroll
        for (int u = 0; u < 4; u++) a[u] = wr[lane + 32 * u];
        float s = 0.0f;
        #pragma unroll
        for (int u = 0; u < 4; u++) s += dot8h(a[u], hv, (lane + 32 * u) * 2);
        #pragma unroll
        for (int o = 16; o; o >>= 1) s += __shfl_xor_sync(0xffffffffu, s, o);
        if (lane == 0) red[warp] = s + b_ih1[r] + b_hh1[r];
        __syncthreads();
        if (tid == 0) {
            const float gi = red[0], gf = red[1], gg = red[2], go = red[3];
            const float cn = sigmoidf_(gf) * __ldcg(&g_c1[j]) + sigmoidf_(gi) * tanhf(gg);
            g_c1[j]        = cn;
            g_h1[pout][j]  = sigmoidf_(go) * tanhf(cn);
        }
        __syncthreads();
    };

    auto dep_task = [&](int j, int pout) {
        const float4* h1p = (const float4*)g_h1[pout];
        for (int k = tid; k < H / 4; k += 128) ((float4*)sv)[k] = __ldcg(h1p + k);
        __syncthreads();

        const int r = warp * H + j;
        const int4* wr = (const int4*)(g_wih2h + (size_t)r * (H + DW));
        const float4* hv = (const float4*)sv;
        int4 a[4];
        #pragma unroll
        for (int u = 0; u < 4; u++) a[u] = wr[lane + 32 * u];
        float s = 0.0f;
        #pragma unroll
        for (int u = 0; u < 4; u++) s += dot8h(a[u], hv, (lane + 32 * u) * 2);
        #pragma unroll
        for (int o = 16; o; o >>= 1) s += __shfl_xor_sync(0xffffffffu, s, o);
        if (lane == 0) red[warp] = s + __ldcg(&g_p2[r]) + b_ih2[r] + b_hh2[r];
        __syncthreads();
        if (tid == 0) {
            const float gi = red[0], gf = red[1], gg = red[2], go = red[3];
            const float cn = sigmoidf_(gf) * __ldcg(&g_c2[j]) + sigmoidf_(gi) * tanhf(gg);
            g_c2[j]        = cn;
            g_h2[pout][j]  = sigmoidf_(go) * tanhf(cn);
        }
        __syncthreads();
    };

    auto logits_task = [&](int s_step, int lt) {
        const int page = s_step & 1;
        const float hs = s_hscale;
        float* out_t = out + (size_t)s_step * VOCAB;
        const int r0 = lt * 16 + warp * 4;
        const int4* w0 = (const int4*)(g_wq + (size_t)(r0 + 0) * (H / 4));
        const int4* w1 = (const int4*)(g_wq + (size_t)(r0 + 1) * (H / 4));
        const int4* w2 = (const int4*)(g_wq + (size_t)(r0 + 2) * (H / 4));
        const int4* w3 = (const int4*)(g_wq + (size_t)(r0 + 3) * (H / 4));
        int s0 = 0, s1 = 0, s2 = 0, s3 = 0;
        #pragma unroll
        for (int k = lane; k < H / 16; k += 32) {
            const int4 h = qh4[k];
            int4 a;
            a = w0[k]; s0 = __dp4a(a.x, h.x, s0); s0 = __dp4a(a.y, h.y, s0);
                       s0 = __dp4a(a.z, h.z, s0); s0 = __dp4a(a.w, h.w, s0);
            a = w1[k]; s1 = __dp4a(a.x, h.x, s1); s1 = __dp4a(a.y, h.y, s1);
                       s1 = __dp4a(a.z, h.z, s1); s1 = __dp4a(a.w, h.w, s1);
            a = w2[k]; s2 = __dp4a(a.x, h.x, s2); s2 = __dp4a(a.y, h.y, s2);
                       s2 = __dp4a(a.z, h.z, s2); s2 = __dp4a(a.w, h.w, s2);
            a = w3[k]; s3 = __dp4a(a.x, h.x, s3); s3 = __dp4a(a.y, h.y, s3);
                       s3 = __dp4a(a.z, h.z, s3); s3 = __dp4a(a.w, h.w, s3);
        }
        s0 = __reduce_add_sync(0xffffffffu, s0);
        s1 = __reduce_add_sync(0xffffffffu, s1);
        s2 = __reduce_add_sync(0xffffffffu, s2);
        s3 = __reduce_add_sync(0xffffffffu, s3);
        if (lane == 0) {
            const float v0 = g_wscale[r0 + 0] * hs * (float)s0 + b_out[r0 + 0];
            const float v1 = g_wscale[r0 + 1] * hs * (float)s1 + b_out[r0 + 1];
            const float v2 = g_wscale[r0 + 2] * hs * (float)s2 + b_out[r0 + 2];
            const float v3 = g_wscale[r0 + 3] * hs * (float)s3 + b_out[r0 + 3];
            out_t[r0 + 0] = v0; out_t[r0 + 1] = v1;
            out_t[r0 + 2] = v2; out_t[r0 + 3] = v3;
            s_rows[warp * 4 + 0] = v0; s_rows[warp * 4 + 1] = v1;
            s_rows[warp * 4 + 2] = v2; s_rows[warp * 4 + 3] = v3;
        }
        __syncthreads();
        if (tid == 0) {
            float m = s_rows[0];
            #pragma unroll
            for (int u = 1; u < 16; u++) m = fmaxf(m, s_rows[u]);
            float sm = 0.0f;
            #pragma unroll
            for (int u = 0; u < 16; u++) sm += expf(s_rows[u] - m);
            g_lmax[page][lt] = m;
            g_lsum[page][lt] = sm;
        }
        __syncthreads();
    };

    auto combine_task = [&](int s_step) {
        const int page = s_step & 1;
        float m = -3.0e38f, sum = 0.0f;
        const int k0 = tid * 16;
        for (int k = k0; k < k0 + 16 && k < LG_TASKS; k++) {
            const float m2 = __ldcg(&g_lmax[page][k]);
            const float s2 = __ldcg(&g_lsum[page][k]);
            if (m2 > m) { sum = sum * __expf(m - m2) + s2; m = m2; }
            else        { sum += s2 * __expf(m2 - m); }
        }
        s_m[tid] = m; s_a[tid] = sum;
        __syncthreads();
        for (int off = 64; off; off >>= 1) {
            if (tid < off) {
                const float m1 = s_m[tid], sA = s_a[tid];
                const float m2 = s_m[tid + off], sB = s_a[tid + off];
                if (m2 > m1) { s_m[tid] = m2; s_a[tid] = sB + sA * __expf(m1 - m2); }
                else         { s_a[tid] = sA + sB * __expf(m2 - m1); }
            }
            __syncthreads();
        }
        if (tid == 0) g_norm[page] = s_m[0] + logf(s_a[0]);
        __syncthreads();
    };

    auto norm_task = [&](int s_step, int k) {
        const float n = __ldcg(&g_norm[s_step & 1]);
        float4* p = (float4*)(out + (size_t)s_step * VOCAB) + k * 1000;
        for (int i = tid; i < 1000; i += 128) {
            float4 v = __ldcg(p + i);
            v.x -= n; v.y -= n; v.z -= n; v.w -= n;
            p[i] = v;
        }
    };

    auto preamble = [&](int pin, int t) {
        const float4* h2p = (const float4*)g_h2[pin];
        const float4 va = __ldcg(h2p + tid);
        const float4 vb = __ldcg(h2p + 128 + tid);
        float am = fmaxf(fmaxf(fabsf(va.x), fabsf(va.y)), fmaxf(fabsf(va.z), fabsf(va.w)));
        am = fmaxf(am, fmaxf(fmaxf(fabsf(vb.x), fabsf(vb.y)), fmaxf(fabsf(vb.z), fabsf(vb.w))));
        float bm = va.x; int bi = 4 * tid;
        if (va.y > bm) { bm = va.y; bi = 4 * tid + 1; }
        if (va.z > bm) { bm = va.z; bi = 4 * tid + 2; }
        if (va.w > bm) { bm = va.w; bi = 4 * tid + 3; }
        if (vb.x > bm) { bm = vb.x; bi = 512 + 4 * tid; }
        if (vb.y > bm) { bm = vb.y; bi = 512 + 4 * tid + 1; }
        if (vb.z > bm) { bm = vb.z; bi = 512 + 4 * tid + 2; }
        if (vb.w > bm) { bm = vb.w; bi = 512 + 4 * tid + 3; }
        s_m[tid] = bm; s_i[tid] = bi; s_a[tid] = am;
        __syncthreads();
        for (int off = 64; off; off >>= 1) {
            if (tid < off) {
                const float v2 = s_m[tid + off]; const int i2 = s_i[tid + off];
                if (v2 > s_m[tid] || (v2 == s_m[tid] && i2 < s_i[tid])) { s_m[tid] = v2; s_i[tid] = i2; }
                s_a[tid] = fmaxf(s_a[tid], s_a[tid + off]);
            }
            __syncthreads();
        }
        if (tid == 0) {
            s_hscale = s_a[0] / 127.0f;
            s_gidx = (t == 0) ? 0 : s_i[0];
        }
        __syncthreads();
        const float inv = (s_a[0] > 0.0f) ? 127.0f / s_a[0] : 0.0f;
        ((int*)qh4)[tid]       = pack4(va, inv);
        ((int*)qh4)[128 + tid] = pack4(vb, inv);
        __syncthreads();
    };

    // ================= main decode loop =================
    for (int t = 0; t < NSTEP; t++) {
        const int pin = t & 1, pout = 1 - pin;

        preamble(pin, t);

        // ---- phase A: lstm2-independent + lstm1 + logits(t-1) chunk + combine(t-2)
        {
            const unsigned nlog = (t >= 1) ? LG_A : 0;
            const unsigned NA = 2048u + nlog + ((t >= 2) ? 1u : 0u);
            for (unsigned i = b; i < NA; i += G) {
                if (i < 1024u)             l2ind_task((int)i, pin);
                else if (i < 2048u)        l1_task((int)i - 1024, pin, pout);
                else if (i < 2048u + nlog) logits_task(t - 1, (int)(i - 2048u));
                else                       combine_task(t - 2);
            }
        }
        gbar(G);

        // ---- phase B: lstm2-dependent + logits(t-1) rest + norm(t-2)
        {
            const unsigned nlog = (t >= 1) ? (LG_TASKS - LG_A) : 0;
            const unsigned NB = 1024u + nlog + ((t >= 2) ? (unsigned)NORM_TASKS : 0u);
            for (unsigned i = b; i < NB; i += G) {
                if (i < 1024u)             dep_task((int)i, pout);
                else if (i < 1024u + nlog) logits_task(t - 1, LG_A + (int)(i - 1024u));
                else                       norm_task(t - 2, (int)(i - 1024u - nlog));
            }
        }
        gbar(G);
    }

    // ================= drain =================
    preamble(NSTEP & 1, NSTEP);
    for (unsigned i = b; i < (unsigned)LG_TASKS + 1u; i += G) {
        if (i < (unsigned)LG_TASKS) logits_task(NSTEP - 1, (int)i);
        else                        combine_task(NSTEP - 2);
    }
    gbar(G);
    for (unsigned i = b; i < (unsigned)NORM_TASKS + 1u; i += G) {
        if (i < (unsigned)NORM_TASKS) norm_task(NSTEP - 2, (int)i);
        else                          combine_task(NSTEP - 1);
    }
    gbar(G);
    for (unsigned i = b; i < (unsigned)NORM_TASKS; i += G) norm_task(NSTEP - 1, (int)i);
}

// ---------------- host driver: two streams (R6-proven topology), 6 launches ----------------
extern "C" void kernel_launch(void* const* d_in, const int* in_sizes, int n_in,
                              void* d_out, int out_size)
{
    const float* vid   = (const float*)d_in[0];
    const float* w_ih1 = (const float*)d_in[1];
    const float* w_hh1 = (const float*)d_in[2];
    const float* b_ih1 = (const float*)d_in[3];
    const float* b_hh1 = (const float*)d_in[4];
    const float* w_ih2 = (const float*)d_in[5];
    const float* w_hh2 = (const float*)d_in[6];
    const float* b_ih2 = (const float*)d_in[7];
    const float* b_hh2 = (const float*)d_in[8];
    const float* emb   = (const float*)d_in[9];
    const float* w_out = (const float*)d_in[10];
    const float* b_out = (const float*)d_in[11];
    float* out = (float*)d_out;

    (void)in_sizes; (void)n_in; (void)out_size;

    static cudaStream_t sB = nullptr;
    static cudaEvent_t evStart = nullptr, evB = nullptr;
    static int smCount = 0;
    if (!sB) {
        cudaStreamCreateWithFlags(&sB, cudaStreamNonBlocking);
        cudaEventCreateWithFlags(&evStart, cudaEventDisableTiming);
        cudaEventCreateWithFlags(&evB,     cudaEventDisableTiming);
        cudaDeviceGetAttribute(&smCount, cudaDevAttrMultiProcessorCount, 0);
    }
    const unsigned G = (unsigned)smCount * 8u;   // divisible by 32 (SM count % 4 == 0)

    k_init<<<1, 1>>>();

    // stream B: int8 w_out cache + fp16 recurrence weights, overlapped with encode
    cudaEventRecord(evStart, 0);
    cudaStreamWaitEvent(sB, evStart, 0);
    k_quant_w<<<VOCAB / 32, 256, 0, sB>>>(w_out);
    k_cvt<<<2048, 256, 0, sB>>>(w_hh1, w_ih2, w_hh2);
    cudaEventRecord(evB, sB);

    // main: encode (fp32 weights)
    k_lstm1_enc<<<H, 128>>>(w_ih1, vid, b_ih1, b_hh1);
    k_l2enc<<<H, 128>>>(w_ih2, b_ih2, b_hh2);

    // decode waits for the caches
    cudaStreamWaitEvent(0, evB, 0);
    k_decode<<<G, 128>>>(b_ih1, b_hh1, b_ih2, b_hh2, emb, b_out, out, G);
}

// round 12
// speedup vs baseline: 1.1027x; 1.1027x over previous
#include <cuda_runtime.h>
#include <cuda_fp16.h>
#include <cstddef>
#include <cstdint>

#define H       1024
#define DV      4096
#define DW      512
#define VOCAB   32000
#define NSTEP   39      // MAX_LEN - 1
#define LG_TASKS 2000   // logits tasks per step, 16 rows each
#define LG_A     640    // logits tasks in phase A (byte balance)
#define NORM_TASKS 8

// ---------------- persistent device state ----------------
__device__ float g_h1[2][H];
__device__ float g_c1[H];
__device__ float g_h2[2][H];
__device__ float g_c2[H];
__device__ float g_p2[4 * H];

__device__ __align__(16) __half g_whh1h[4 * H * H];
__device__ __align__(16) __half g_wih2h[4 * H * (H + DW)];
__device__ __align__(16) __half g_whh2h[4 * H * H];

__device__ int   g_wq[VOCAB * (H / 4)];
__device__ float g_wscale[VOCAB];

__device__ float g_lmax[2][LG_TASKS];
__device__ float g_lsum[2][LG_TASKS];
__device__ float g_norm[2];

__device__ unsigned g_cnt[32];
__device__ unsigned g_mst;
__device__ unsigned g_gen;

__device__ __forceinline__ float sigmoidf_(float x) { return 1.0f / (1.0f + expf(-x)); }

__global__ void k_init()
{
    for (int i = 0; i < 32; i++) g_cnt[i] = 0;
    g_mst = 0; g_gen = 0;
}

// ---------------- hierarchical grid barrier (32 | G) ----------------
__device__ __forceinline__ void gbar(unsigned G)
{
    __syncthreads();
    if (threadIdx.x == 0) {
        __threadfence();
        const unsigned gen = *(volatile unsigned*)&g_gen;
        const unsigned sub = blockIdx.x & 31u;
        const unsigned subTarget = G >> 5;
        if (atomicAdd(&g_cnt[sub], 1u) == subTarget - 1u) {
            atomicExch(&g_cnt[sub], 0u);
            if (atomicAdd(&g_mst, 1u) == 31u) {
                atomicExch(&g_mst, 0u);
                __threadfence();
                atomicAdd(&g_gen, 1u);
            } else {
                while (*(volatile unsigned*)&g_gen == gen) __nanosleep(32);
            }
        } else {
            while (*(volatile unsigned*)&g_gen == gen) __nanosleep(64);
        }
        __threadfence();
    }
    __syncthreads();
}

// ---------------- one-time caches (stream B) ----------------
__global__ void k_cvt(const float* __restrict__ w_hh1, const float* __restrict__ w_ih2,
                      const float* __restrict__ w_hh2)
{
    const int stride = gridDim.x * blockDim.x;
    const int t0 = blockIdx.x * blockDim.x + threadIdx.x;
    const int n1 = 4 * H * H / 2, n2 = 4 * H * (H + DW) / 2;
    const float2* s1 = (const float2*)w_hh1;  __half2* d1 = (__half2*)g_whh1h;
    const float2* s2 = (const float2*)w_ih2;  __half2* d2 = (__half2*)g_wih2h;
    const float2* s3 = (const float2*)w_hh2;  __half2* d3 = (__half2*)g_whh2h;
    for (int i = t0; i < n1; i += stride) d1[i] = __float22half2_rn(s1[i]);
    for (int i = t0; i < n2; i += stride) d2[i] = __float22half2_rn(s2[i]);
    for (int i = t0; i < n1; i += stride) d3[i] = __float22half2_rn(s3[i]);
}

__global__ void k_quant_w(const float* __restrict__ w)
{
    const int warp = threadIdx.x >> 5;
    const int lane = threadIdx.x & 31;
    const int row0 = blockIdx.x * 32 + warp * 4;

    for (int rr = 0; rr < 4; rr++) {
        const int row = row0 + rr;
        const float4* wr = (const float4*)(w + (size_t)row * H);
        float4 v[8];
        float m = 0.0f;
        #pragma unroll
        for (int i = 0; i < 8; i++) {
            v[i] = wr[lane + 32 * i];
            m = fmaxf(m, fmaxf(fmaxf(fabsf(v[i].x), fabsf(v[i].y)),
                               fmaxf(fabsf(v[i].z), fabsf(v[i].w))));
        }
        #pragma unroll
        for (int o = 16; o; o >>= 1) m = fmaxf(m, __shfl_xor_sync(0xffffffffu, m, o));
        const float inv = (m > 0.0f) ? 127.0f / m : 0.0f;
        #pragma unroll
        for (int i = 0; i < 8; i++) {
            const int a = (int)rintf(v[i].x * inv);
            const int b = (int)rintf(v[i].y * inv);
            const int c = (int)rintf(v[i].z * inv);
            const int d = (int)rintf(v[i].w * inv);
            g_wq[row * (H / 4) + lane + 32 * i] =
                (a & 0xFF) | ((b & 0xFF) << 8) | ((c & 0xFF) << 16) | ((d & 0xFF) << 24);
        }
        if (lane == 0) g_wscale[row] = m / 127.0f;
    }
}

// ---------------- encode kernels (fp32 weights) ----------------
__global__ void k_lstm1_enc(const float* __restrict__ w_ih, const float* __restrict__ x,
                            const float* __restrict__ b_ih, const float* __restrict__ b_hh)
{
    __shared__ float sx[DV];
    __shared__ float red[4];
    const int j = blockIdx.x, tid = threadIdx.x, warp = tid >> 5, lane = tid & 31;

    for (int i = tid; i < DV; i += 128) sx[i] = x[i];
    __syncthreads();

    const int r = warp * H + j;
    const float4* wr = (const float4*)(w_ih + (size_t)r * DV);
    const float4* xv = (const float4*)sx;
    float s = 0.0f;
    #pragma unroll
    for (int k0 = 0; k0 < DV / 4; k0 += 256) {
        float4 a[8];
        #pragma unroll
        for (int u = 0; u < 8; u++) a[u] = wr[k0 + lane + 32 * u];
        #pragma unroll
        for (int u = 0; u < 8; u++) {
            const float4 b = xv[k0 + lane + 32 * u];
            s += a[u].x * b.x + a[u].y * b.y + a[u].z * b.z + a[u].w * b.w;
        }
    }
    #pragma unroll
    for (int o = 16; o; o >>= 1) s += __shfl_xor_sync(0xffffffffu, s, o);
    if (lane == 0) red[warp] = s + b_ih[r] + b_hh[r];
    __syncthreads();

    if (tid == 0) {
        const float gi = red[0], gf = red[1], gg = red[2], go = red[3];
        const float cn = sigmoidf_(gi) * tanhf(gg);
        g_c1[j]    = cn;
        g_h1[0][j] = sigmoidf_(go) * tanhf(cn);
    }
}

__global__ void k_l2enc(const float* __restrict__ w_ih,
                        const float* __restrict__ b_ih, const float* __restrict__ b_hh)
{
    __shared__ float sh[H];
    __shared__ float red[4];
    const int j = blockIdx.x, tid = threadIdx.x, warp = tid >> 5, lane = tid & 31;

    for (int i = tid; i < H; i += 128) sh[i] = g_h1[0][i];
    __syncthreads();

    const int r = warp * H + j;
    const float4* wr = (const float4*)(w_ih + (size_t)r * (H + DW));
    const float4* hv = (const float4*)sh;
    float4 a[8];
    #pragma unroll
    for (int u = 0; u < 8; u++) a[u] = wr[lane + 32 * u];
    float s = 0.0f;
    #pragma unroll
    for (int u = 0; u < 8; u++) {
        const float4 b = hv[lane + 32 * u];
        s += a[u].x * b.x + a[u].y * b.y + a[u].z * b.z + a[u].w * b.w;
    }
    #pragma unroll
    for (int o = 16; o; o >>= 1) s += __shfl_xor_sync(0xffffffffu, s, o);
    if (lane == 0) red[warp] = s + b_ih[r] + b_hh[r];
    __syncthreads();

    if (tid == 0) {
        const float gi = red[0], gf = red[1], gg = red[2], go = red[3];
        const float cn = sigmoidf_(gi) * tanhf(gg);
        g_c2[j]    = cn;
        g_h2[0][j] = sigmoidf_(go) * tanhf(cn);
    }
}

// ---------------- helpers ----------------
__device__ __forceinline__ int pack4(float4 v, float inv)
{
    const int a = (int)rintf(v.x * inv);
    const int b = (int)rintf(v.y * inv);
    const int c = (int)rintf(v.z * inv);
    const int d = (int)rintf(v.w * inv);
    return (a & 0xFF) | ((b & 0xFF) << 8) | ((c & 0xFF) << 16) | ((d & 0xFF) << 24);
}

__device__ __forceinline__ float dot8h(int4 p, const float4* hv4, int pairIdx)
{
    const float4 hA = hv4[pairIdx];
    const float4 hB = hv4[pairIdx + 1];
    const float2 w0 = __half22float2(*(__half2*)&p.x);
    const float2 w1 = __half22float2(*(__half2*)&p.y);
    const float2 w2 = __half22float2(*(__half2*)&p.z);
    const float2 w3 = __half22float2(*(__half2*)&p.w);
    return w0.x * hA.x + w0.y * hA.y + w1.x * hA.z + w1.y * hA.w
         + w2.x * hB.x + w2.y * hB.y + w3.x * hB.z + w3.y * hB.w;
}

// ---------------- persistent decode kernel ----------------
__global__ void __launch_bounds__(128, 8)
k_decode(const float* __restrict__ b_ih1, const float* __restrict__ b_hh1,
         const float* __restrict__ b_ih2, const float* __restrict__ b_hh2,
         const float* __restrict__ emb,  const float* __restrict__ b_out,
         float* __restrict__ out, unsigned G)
{
    __shared__ float sv[2 * H + DW];   // [0,H): h1 | [H,2H): h2 | [2H,2H+DW): emb
    __shared__ int4  qh4[H / 16];
    __shared__ float red[4];
    __shared__ float s_m[4];
    __shared__ int   s_i[4];
    __shared__ float s_a[4];
    __shared__ float sm128[128];
    __shared__ float sa128[128];
    __shared__ float s_rows[16];
    __shared__ float s_hscale, s_inv;
    __shared__ int   s_gidx;

    const unsigned b   = blockIdx.x;
    const int tid  = threadIdx.x;
    const int warp = tid >> 5;
    const int lane = tid & 31;

    // -------- fused phase-A recurrence task: lstm1(row) + lstm2-independent(row) --------
    auto fusedA_task = [&](int j, int pin, int pout) {
        const int r = warp * H + j;
        // issue ALL weight loads first (reg-bound, independent of staging)
        const int4* w1p = (const int4*)(g_whh1h + (size_t)r * H);
        const int4* w2p = (const int4*)(g_whh2h + (size_t)r * H);
        const int4* wep = (const int4*)(g_wih2h + (size_t)r * (H + DW) + H);
        int4 a1[4], a2[4], e2[2];
        #pragma unroll
        for (int u = 0; u < 4; u++) a1[u] = w1p[lane + 32 * u];
        #pragma unroll
        for (int u = 0; u < 4; u++) a2[u] = w2p[lane + 32 * u];
        #pragma unroll
        for (int u = 0; u < 2; u++) e2[u] = wep[lane + 32 * u];

        // stage h1, h2, emb (overlaps with weight-load latency)
        {
            const float4* h1p = (const float4*)g_h1[pin];
            const float4* h2p = (const float4*)g_h2[pin];
            float4* s4 = (float4*)sv;
            s4[tid]           = __ldcg(h1p + tid);
            s4[128 + tid]     = __ldcg(h1p + 128 + tid);
            s4[256 + tid]     = __ldcg(h2p + tid);
            s4[384 + tid]     = __ldcg(h2p + 128 + tid);
            const float4* ev = (const float4*)(emb + (size_t)s_gidx * DW);
            s4[512 + tid]     = ev[tid];
        }
        __syncthreads();

        const float4* hv = (const float4*)sv;
        float s1 = 0.0f, s2 = 0.0f;
        #pragma unroll
        for (int u = 0; u < 4; u++) s1 += dot8h(a1[u], hv, (lane + 32 * u) * 2);
        #pragma unroll
        for (int u = 0; u < 4; u++) s2 += dot8h(a2[u], hv, H / 4 + (lane + 32 * u) * 2);
        #pragma unroll
        for (int u = 0; u < 2; u++) s2 += dot8h(e2[u], hv, 2 * H / 4 + (lane + 32 * u) * 2);
        #pragma unroll
        for (int o = 16; o; o >>= 1) {
            s1 += __shfl_xor_sync(0xffffffffu, s1, o);
            s2 += __shfl_xor_sync(0xffffffffu, s2, o);
        }
        if (lane == 0) {
            red[warp] = s1 + b_ih1[r] + b_hh1[r];
            g_p2[r]   = s2;
        }
        __syncthreads();
        if (tid == 0) {
            const float gi = red[0], gf = red[1], gg = red[2], go = red[3];
            const float cn = sigmoidf_(gf) * __ldcg(&g_c1[j]) + sigmoidf_(gi) * tanhf(gg);
            g_c1[j]       = cn;
            g_h1[pout][j] = sigmoidf_(go) * tanhf(cn);
        }
        __syncthreads();
    };

    // -------- phase-B dependent task: w_ih2[:, :H] * h1_new + p2, gate h2 --------
    auto dep_task = [&](int j, int pout) {
        const int r = warp * H + j;
        const int4* wr = (const int4*)(g_wih2h + (size_t)r * (H + DW));
        int4 a[4];
        #pragma unroll
        for (int u = 0; u < 4; u++) a[u] = wr[lane + 32 * u];

        {
            const float4* h1p = (const float4*)g_h1[pout];
            float4* s4 = (float4*)sv;
            s4[tid]       = __ldcg(h1p + tid);
            s4[128 + tid] = __ldcg(h1p + 128 + tid);
        }
        __syncthreads();

        const float4* hv = (const float4*)sv;
        float s = 0.0f;
        #pragma unroll
        for (int u = 0; u < 4; u++) s += dot8h(a[u], hv, (lane + 32 * u) * 2);
        #pragma unroll
        for (int o = 16; o; o >>= 1) s += __shfl_xor_sync(0xffffffffu, s, o);
        if (lane == 0) red[warp] = s + __ldcg(&g_p2[r]) + b_ih2[r] + b_hh2[r];
        __syncthreads();
        if (tid == 0) {
            const float gi = red[0], gf = red[1], gg = red[2], go = red[3];
            const float cn = sigmoidf_(gf) * __ldcg(&g_c2[j]) + sigmoidf_(gi) * tanhf(gg);
            g_c2[j]       = cn;
            g_h2[pout][j] = sigmoidf_(go) * tanhf(cn);
        }
        __syncthreads();
    };

    auto logits_task = [&](int s_step, int lt) {
        const int page = s_step & 1;
        const float hs = s_hscale;
        float* out_t = out + (size_t)s_step * VOCAB;
        const int r0 = lt * 16 + warp * 4;
        const int4* w0 = (const int4*)(g_wq + (size_t)(r0 + 0) * (H / 4));
        const int4* w1 = (const int4*)(g_wq + (size_t)(r0 + 1) * (H / 4));
        const int4* w2 = (const int4*)(g_wq + (size_t)(r0 + 2) * (H / 4));
        const int4* w3 = (const int4*)(g_wq + (size_t)(r0 + 3) * (H / 4));
        int s0 = 0, s1 = 0, s2 = 0, s3 = 0;
        #pragma unroll
        for (int k = lane; k < H / 16; k += 32) {
            const int4 h = qh4[k];
            int4 a;
            a = w0[k]; s0 = __dp4a(a.x, h.x, s0); s0 = __dp4a(a.y, h.y, s0);
                       s0 = __dp4a(a.z, h.z, s0); s0 = __dp4a(a.w, h.w, s0);
            a = w1[k]; s1 = __dp4a(a.x, h.x, s1); s1 = __dp4a(a.y, h.y, s1);
                       s1 = __dp4a(a.z, h.z, s1); s1 = __dp4a(a.w, h.w, s1);
            a = w2[k]; s2 = __dp4a(a.x, h.x, s2); s2 = __dp4a(a.y, h.y, s2);
                       s2 = __dp4a(a.z, h.z, s2); s2 = __dp4a(a.w, h.w, s2);
            a = w3[k]; s3 = __dp4a(a.x, h.x, s3); s3 = __dp4a(a.y, h.y, s3);
                       s3 = __dp4a(a.z, h.z, s3); s3 = __dp4a(a.w, h.w, s3);
        }
        s0 = __reduce_add_sync(0xffffffffu, s0);
        s1 = __reduce_add_sync(0xffffffffu, s1);
        s2 = __reduce_add_sync(0xffffffffu, s2);
        s3 = __reduce_add_sync(0xffffffffu, s3);
        if (lane == 0) {
            const float v0 = g_wscale[r0 + 0] * hs * (float)s0 + b_out[r0 + 0];
            const float v1 = g_wscale[r0 + 1] * hs * (float)s1 + b_out[r0 + 1];
            const float v2 = g_wscale[r0 + 2] * hs * (float)s2 + b_out[r0 + 2];
            const float v3 = g_wscale[r0 + 3] * hs * (float)s3 + b_out[r0 + 3];
            out_t[r0 + 0] = v0; out_t[r0 + 1] = v1;
            out_t[r0 + 2] = v2; out_t[r0 + 3] = v3;
            s_rows[warp * 4 + 0] = v0; s_rows[warp * 4 + 1] = v1;
            s_rows[warp * 4 + 2] = v2; s_rows[warp * 4 + 3] = v3;
        }
        __syncthreads();
        if (tid == 0) {
            float m = s_rows[0];
            #pragma unroll
            for (int u = 1; u < 16; u++) m = fmaxf(m, s_rows[u]);
            float sm = 0.0f;
            #pragma unroll
            for (int u = 0; u < 16; u++) sm += expf(s_rows[u] - m);
            g_lmax[page][lt] = m;
            g_lsum[page][lt] = sm;
        }
        __syncthreads();
    };

    auto combine_task = [&](int s_step) {
        const int page = s_step & 1;
        float m = -3.0e38f, sum = 0.0f;
        const int k0 = tid * 16;
        for (int k = k0; k < k0 + 16 && k < LG_TASKS; k++) {
            const float m2 = __ldcg(&g_lmax[page][k]);
            const float s2 = __ldcg(&g_lsum[page][k]);
            if (m2 > m) { sum = sum * __expf(m - m2) + s2; m = m2; }
            else        { sum += s2 * __expf(m2 - m); }
        }
        sm128[tid] = m; sa128[tid] = sum;
        __syncthreads();
        for (int off = 64; off; off >>= 1) {
            if (tid < off) {
                const float m1 = sm128[tid], sA = sa128[tid];
                const float m2 = sm128[tid + off], sB = sa128[tid + off];
                if (m2 > m1) { sm128[tid] = m2; sa128[tid] = sB + sA * __expf(m1 - m2); }
                else         { sa128[tid] = sA + sB * __expf(m2 - m1); }
            }
            __syncthreads();
        }
        if (tid == 0) g_norm[page] = sm128[0] + logf(sa128[0]);
        __syncthreads();
    };

    auto norm_task = [&](int s_step, int k) {
        const float n = __ldcg(&g_norm[s_step & 1]);
        float4* p = (float4*)(out + (size_t)s_step * VOCAB) + k * 1000;
        for (int i = tid; i < 1000; i += 128) {
            float4 v = __ldcg(p + i);
            v.x -= n; v.y -= n; v.z -= n; v.w -= n;
            p[i] = v;
        }
    };

    auto preamble = [&](int pin, int t) {
        // per-block argmax + absmax + int8 quant of h2[pin] (warp-shuffle reduce, 2 syncs)
        const float4* h2p = (const float4*)g_h2[pin];
        const float4 va = __ldcg(h2p + tid);
        const float4 vb = __ldcg(h2p + 128 + tid);
        float am = fmaxf(fmaxf(fabsf(va.x), fabsf(va.y)), fmaxf(fabsf(va.z), fabsf(va.w)));
        am = fmaxf(am, fmaxf(fmaxf(fabsf(vb.x), fabsf(vb.y)), fmaxf(fabsf(vb.z), fabsf(vb.w))));
        float bm = va.x; int bi = 4 * tid;
        if (va.y > bm) { bm = va.y; bi = 4 * tid + 1; }
        if (va.z > bm) { bm = va.z; bi = 4 * tid + 2; }
        if (va.w > bm) { bm = va.w; bi = 4 * tid + 3; }
        if (vb.x > bm) { bm = vb.x; bi = 512 + 4 * tid; }
        if (vb.y > bm) { bm = vb.y; bi = 512 + 4 * tid + 1; }
        if (vb.z > bm) { bm = vb.z; bi = 512 + 4 * tid + 2; }
        if (vb.w > bm) { bm = vb.w; bi = 512 + 4 * tid + 3; }
        #pragma unroll
        for (int o = 16; o; o >>= 1) {
            const float v2 = __shfl_xor_sync(0xffffffffu, bm, o);
            const int   i2 = __shfl_xor_sync(0xffffffffu, bi, o);
            if (v2 > bm || (v2 == bm && i2 < bi)) { bm = v2; bi = i2; }
            am = fmaxf(am, __shfl_xor_sync(0xffffffffu, am, o));
        }
        if (lane == 0) { s_m[warp] = bm; s_i[warp] = bi; s_a[warp] = am; }
        __syncthreads();
        if (tid == 0) {
            float fm = s_m[0]; int fi = s_i[0];
            float fa = s_a[0];
            #pragma unroll
            for (int u = 1; u < 4; u++) {
                if (s_m[u] > fm || (s_m[u] == fm && s_i[u] < fi)) { fm = s_m[u]; fi = s_i[u]; }
                fa = fmaxf(fa, s_a[u]);
            }
            s_hscale = fa / 127.0f;
            s_inv    = (fa > 0.0f) ? 127.0f / fa : 0.0f;
            s_gidx   = (t == 0) ? 0 : fi;
        }
        __syncthreads();
        const float inv = s_inv;
        ((int*)qh4)[tid]       = pack4(va, inv);
        ((int*)qh4)[128 + tid] = pack4(vb, inv);
        __syncthreads();
    };

    // ================= main decode loop =================
    for (int t = 0; t < NSTEP; t++) {
        const int pin = t & 1, pout = 1 - pin;

        preamble(pin, t);

        // ---- phase A: fused recurrence (1024) + logits(t-1) chunk + combine(t-2)
        {
            const unsigned nlog = (t >= 1) ? LG_A : 0;
            const unsigned NA = 1024u + nlog + ((t >= 2) ? 1u : 0u);
            for (unsigned i = b; i < NA; i += G) {
                if (i < 1024u)             fusedA_task((int)i, pin, pout);
                else if (i < 1024u + nlog) logits_task(t - 1, (int)(i - 1024u));
                else                       combine_task(t - 2);
            }
        }
        gbar(G);

        // ---- phase B: lstm2-dependent (1024) + logits(t-1) rest + norm(t-2)
        {
            const unsigned nlog = (t >= 1) ? (LG_TASKS - LG_A) : 0;
            const unsigned NB = 1024u + nlog + ((t >= 2) ? (unsigned)NORM_TASKS : 0u);
            for (unsigned i = b; i < NB; i += G) {
                if (i < 1024u)             dep_task((int)i, pout);
                else if (i < 1024u + nlog) logits_task(t - 1, LG_A + (int)(i - 1024u));
                else                       norm_task(t - 2, (int)(i - 1024u - nlog));
            }
        }
        gbar(G);
    }

    // ================= drain =================
    preamble(NSTEP & 1, NSTEP);
    for (unsigned i = b; i < (unsigned)LG_TASKS + 1u; i += G) {
        if (i < (unsigned)LG_TASKS) logits_task(NSTEP - 1, (int)i);
        else                        combine_task(NSTEP - 2);
    }
    gbar(G);
    for (unsigned i = b; i < (unsigned)NORM_TASKS + 1u; i += G) {
        if (i < (unsigned)NORM_TASKS) norm_task(NSTEP - 2, (int)i);
        else                          combine_task(NSTEP - 1);
    }
    gbar(G);
    for (unsigned i = b; i < (unsigned)NORM_TASKS; i += G) norm_task(NSTEP - 1, (int)i);
}

// ---------------- host driver ----------------
extern "C" void kernel_launch(void* const* d_in, const int* in_sizes, int n_in,
                              void* d_out, int out_size)
{
    const float* vid   = (const float*)d_in[0];
    const float* w_ih1 = (const float*)d_in[1];
    const float* w_hh1 = (const float*)d_in[2];
    const float* b_ih1 = (const float*)d_in[3];
    const float* b_hh1 = (const float*)d_in[4];
    const float* w_ih2 = (const float*)d_in[5];
    const float* w_hh2 = (const float*)d_in[6];
    const float* b_ih2 = (const float*)d_in[7];
    const float* b_hh2 = (const float*)d_in[8];
    const float* emb   = (const float*)d_in[9];
    const float* w_out = (const float*)d_in[10];
    const float* b_out = (const float*)d_in[11];
    float* out = (float*)d_out;

    (void)in_sizes; (void)n_in; (void)out_size;

    static cudaStream_t sB = nullptr;
    static cudaEvent_t evStart = nullptr, evB = nullptr;
    static int smCount = 0;
    if (!sB) {
        cudaStreamCreateWithFlags(&sB, cudaStreamNonBlocking);
        cudaEventCreateWithFlags(&evStart, cudaEventDisableTiming);
        cudaEventCreateWithFlags(&evB,     cudaEventDisableTiming);
        cudaDeviceGetAttribute(&smCount, cudaDevAttrMultiProcessorCount, 0);
    }
    const unsigned G = (unsigned)smCount * 8u;   // divisible by 32 on GB300

    k_init<<<1, 1>>>();

    cudaEventRecord(evStart, 0);
    cudaStreamWaitEvent(sB, evStart, 0);
    k_quant_w<<<VOCAB / 32, 256, 0, sB>>>(w_out);
    k_cvt<<<2048, 256, 0, sB>>>(w_hh1, w_ih2, w_hh2);
    cudaEventRecord(evB, sB);

    k_lstm1_enc<<<H, 128>>>(w_ih1, vid, b_ih1, b_hh1);
    k_l2enc<<<H, 128>>>(w_ih2, b_ih2, b_hh2);

    cudaStreamWaitEvent(0, evB, 0);
    k_decode<<<G, 128>>>(b_ih1, b_hh1, b_ih2, b_hh2, emb, b_out, out, G);
}

// round 14
// speedup vs baseline: 1.1048x; 1.0019x over previous
#include <cuda_runtime.h>
#include <cuda_fp16.h>
#include <cstddef>
#include <cstdint>

#define H       1024
#define DV      4096
#define DW      512
#define VOCAB   32000
#define NSTEP   39      // MAX_LEN - 1
#define LG_TASKS 1000   // logits tasks per step, 32 rows each
#define LG_A     400    // logits tasks in phase A
#define NORM_TASKS 8

// ---------------- persistent device state ----------------
__device__ float g_h1[2][H];
__device__ float g_c1[H];
__device__ float g_h2[2][H];
__device__ float g_c2[H];
__device__ float g_p2[4 * H];

__device__ __align__(16) __half g_whh1h[4 * H * H];
__device__ __align__(16) __half g_wih2h[4 * H * (H + DW)];
__device__ __align__(16) __half g_whh2h[4 * H * H];

__device__ int   g_wq[VOCAB * (H / 4)];
__device__ float g_wscale[VOCAB];

__device__ float g_lmax[2][LG_TASKS];
__device__ float g_lsum[2][LG_TASKS];
__device__ float g_norm[2];

__device__ unsigned g_cnt[32];
__device__ unsigned g_mst;
__device__ unsigned g_gen;

__device__ __forceinline__ float sigmoidf_(float x) { return 1.0f / (1.0f + expf(-x)); }

__global__ void k_init()
{
    for (int i = 0; i < 32; i++) g_cnt[i] = 0;
    g_mst = 0; g_gen = 0;
}

// ---------------- hierarchical grid barrier (32 | G) ----------------
__device__ __forceinline__ void gbar(unsigned G)
{
    __syncthreads();
    if (threadIdx.x == 0) {
        __threadfence();
        const unsigned gen = *(volatile unsigned*)&g_gen;
        const unsigned sub = blockIdx.x & 31u;
        const unsigned subTarget = G >> 5;
        if (atomicAdd(&g_cnt[sub], 1u) == subTarget - 1u) {
            atomicExch(&g_cnt[sub], 0u);
            if (atomicAdd(&g_mst, 1u) == 31u) {
                atomicExch(&g_mst, 0u);
                __threadfence();
                atomicAdd(&g_gen, 1u);
            } else {
                while (*(volatile unsigned*)&g_gen == gen) __nanosleep(32);
            }
        } else {
            while (*(volatile unsigned*)&g_gen == gen) __nanosleep(64);
        }
        __threadfence();
    }
    __syncthreads();
}

// ---------------- one-time caches (stream B) ----------------
__global__ void k_cvt(const float* __restrict__ w_hh1, const float* __restrict__ w_ih2,
                      const float* __restrict__ w_hh2)
{
    const int stride = gridDim.x * blockDim.x;
    const int t0 = blockIdx.x * blockDim.x + threadIdx.x;
    const int n1 = 4 * H * H / 2, n2 = 4 * H * (H + DW) / 2;
    const float2* s1 = (const float2*)w_hh1;  __half2* d1 = (__half2*)g_whh1h;
    const float2* s2 = (const float2*)w_ih2;  __half2* d2 = (__half2*)g_wih2h;
    const float2* s3 = (const float2*)w_hh2;  __half2* d3 = (__half2*)g_whh2h;
    for (int i = t0; i < n1; i += stride) d1[i] = __float22half2_rn(s1[i]);
    for (int i = t0; i < n2; i += stride) d2[i] = __float22half2_rn(s2[i]);
    for (int i = t0; i < n1; i += stride) d3[i] = __float22half2_rn(s3[i]);
}

__global__ void k_quant_w(const float* __restrict__ w)
{
    const int warp = threadIdx.x >> 5;
    const int lane = threadIdx.x & 31;
    const int row0 = blockIdx.x * 32 + warp * 4;

    for (int rr = 0; rr < 4; rr++) {
        const int row = row0 + rr;
        const float4* wr = (const float4*)(w + (size_t)row * H);
        float4 v[8];
        float m = 0.0f;
        #pragma unroll
        for (int i = 0; i < 8; i++) {
            v[i] = wr[lane + 32 * i];
            m = fmaxf(m, fmaxf(fmaxf(fabsf(v[i].x), fabsf(v[i].y)),
                               fmaxf(fabsf(v[i].z), fabsf(v[i].w))));
        }
        #pragma unroll
        for (int o = 16; o; o >>= 1) m = fmaxf(m, __shfl_xor_sync(0xffffffffu, m, o));
        const float inv = (m > 0.0f) ? 127.0f / m : 0.0f;
        #pragma unroll
        for (int i = 0; i < 8; i++) {
            const int a = (int)rintf(v[i].x * inv);
            const int b = (int)rintf(v[i].y * inv);
            const int c = (int)rintf(v[i].z * inv);
            const int d = (int)rintf(v[i].w * inv);
            g_wq[row * (H / 4) + lane + 32 * i] =
                (a & 0xFF) | ((b & 0xFF) << 8) | ((c & 0xFF) << 16) | ((d & 0xFF) << 24);
        }
        if (lane == 0) g_wscale[row] = m / 127.0f;
    }
}

// ---------------- encode kernels (fp32 weights) ----------------
__global__ void k_lstm1_enc(const float* __restrict__ w_ih, const float* __restrict__ x,
                            const float* __restrict__ b_ih, const float* __restrict__ b_hh)
{
    __shared__ float sx[DV];
    __shared__ float red[4];
    const int j = blockIdx.x, tid = threadIdx.x, warp = tid >> 5, lane = tid & 31;

    for (int i = tid; i < DV; i += 128) sx[i] = x[i];
    __syncthreads();

    const int r = warp * H + j;
    const float4* wr = (const float4*)(w_ih + (size_t)r * DV);
    const float4* xv = (const float4*)sx;
    float s = 0.0f;
    #pragma unroll
    for (int k0 = 0; k0 < DV / 4; k0 += 256) {
        float4 a[8];
        #pragma unroll
        for (int u = 0; u < 8; u++) a[u] = wr[k0 + lane + 32 * u];
        #pragma unroll
        for (int u = 0; u < 8; u++) {
            const float4 b = xv[k0 + lane + 32 * u];
            s += a[u].x * b.x + a[u].y * b.y + a[u].z * b.z + a[u].w * b.w;
        }
    }
    #pragma unroll
    for (int o = 16; o; o >>= 1) s += __shfl_xor_sync(0xffffffffu, s, o);
    if (lane == 0) red[warp] = s + b_ih[r] + b_hh[r];
    __syncthreads();

    if (tid == 0) {
        const float gi = red[0], gf = red[1], gg = red[2], go = red[3];
        const float cn = sigmoidf_(gi) * tanhf(gg);
        g_c1[j]    = cn;
        g_h1[0][j] = sigmoidf_(go) * tanhf(cn);
    }
}

__global__ void k_l2enc(const float* __restrict__ w_ih,
                        const float* __restrict__ b_ih, const float* __restrict__ b_hh)
{
    __shared__ float sh[H];
    __shared__ float red[4];
    const int j = blockIdx.x, tid = threadIdx.x, warp = tid >> 5, lane = tid & 31;

    for (int i = tid; i < H; i += 128) sh[i] = g_h1[0][i];
    __syncthreads();

    const int r = warp * H + j;
    const float4* wr = (const float4*)(w_ih + (size_t)r * (H + DW));
    const float4* hv = (const float4*)sh;
    float4 a[8];
    #pragma unroll
    for (int u = 0; u < 8; u++) a[u] = wr[lane + 32 * u];
    float s = 0.0f;
    #pragma unroll
    for (int u = 0; u < 8; u++) {
        const float4 b = hv[lane + 32 * u];
        s += a[u].x * b.x + a[u].y * b.y + a[u].z * b.z + a[u].w * b.w;
    }
    #pragma unroll
    for (int o = 16; o; o >>= 1) s += __shfl_xor_sync(0xffffffffu, s, o);
    if (lane == 0) red[warp] = s + b_ih[r] + b_hh[r];
    __syncthreads();

    if (tid == 0) {
        const float gi = red[0], gf = red[1], gg = red[2], go = red[3];
        const float cn = sigmoidf_(gi) * tanhf(gg);
        g_c2[j]    = cn;
        g_h2[0][j] = sigmoidf_(go) * tanhf(cn);
    }
}

// ---------------- helpers ----------------
__device__ __forceinline__ int pack4(float4 v, float inv)
{
    const int a = (int)rintf(v.x * inv);
    const int b = (int)rintf(v.y * inv);
    const int c = (int)rintf(v.z * inv);
    const int d = (int)rintf(v.w * inv);
    return (a & 0xFF) | ((b & 0xFF) << 8) | ((c & 0xFF) << 16) | ((d & 0xFF) << 24);
}

__device__ __forceinline__ float dot8h(int4 p, const float4* hv4, int pairIdx)
{
    const float4 hA = hv4[pairIdx];
    const float4 hB = hv4[pairIdx + 1];
    const float2 w0 = __half22float2(*(__half2*)&p.x);
    const float2 w1 = __half22float2(*(__half2*)&p.y);
    const float2 w2 = __half22float2(*(__half2*)&p.z);
    const float2 w3 = __half22float2(*(__half2*)&p.w);
    return w0.x * hA.x + w0.y * hA.y + w1.x * hA.z + w1.y * hA.w
         + w2.x * hB.x + w2.y * hB.y + w3.x * hB.z + w3.y * hB.w;
}

// ---------------- persistent decode kernel ----------------
__global__ void __launch_bounds__(128, 8)
k_decode(const float* __restrict__ b_ih1, const float* __restrict__ b_hh1,
         const float* __restrict__ b_ih2, const float* __restrict__ b_hh2,
         const float* __restrict__ emb,  const float* __restrict__ b_out,
         float* __restrict__ out, unsigned G)
{
    __shared__ float sv[2 * H + DW];   // [0,H): h1 | [H,2H): h2 | [2H,2H+DW): emb
    __shared__ int4  qh4[H / 16];
    __shared__ float red[4];
    __shared__ float s_m[4];
    __shared__ int   s_i[4];
    __shared__ float s_a[4];
    __shared__ float sm128[128];
    __shared__ float sa128[128];
    __shared__ float s_rows[32];
    __shared__ float s_hscale, s_inv;
    __shared__ int   s_gidx;

    const unsigned b   = blockIdx.x;
    const int tid  = threadIdx.x;
    const int warp = tid >> 5;
    const int lane = tid & 31;

    // -------- phase-A fused 2-row task: rows {jb, jb+512} of lstm1 + lstm2-independent ----
    auto fused2_task = [&](int jb, int pin, int pout) {
        // stage h1, h2, emb once
        {
            const float4* h1p = (const float4*)g_h1[pin];
            const float4* h2p = (const float4*)g_h2[pin];
            float4* s4 = (float4*)sv;
            s4[tid]       = __ldcg(h1p + tid);
            s4[128 + tid] = __ldcg(h1p + 128 + tid);
            s4[256 + tid] = __ldcg(h2p + tid);
            s4[384 + tid] = __ldcg(h2p + 128 + tid);
            const float4* ev = (const float4*)(emb + (size_t)s_gidx * DW);
            s4[512 + tid] = ev[tid];
        }
        __syncthreads();
        const float4* hv = (const float4*)sv;

        #pragma unroll
        for (int half = 0; half < 2; half++) {
            const int j = jb + half * 512;
            const int r = warp * H + j;
            const int4* w1p = (const int4*)(g_whh1h + (size_t)r * H);
            const int4* w2p = (const int4*)(g_whh2h + (size_t)r * H);
            const int4* wep = (const int4*)(g_wih2h + (size_t)r * (H + DW) + H);
            int4 a1[4], a2[4], e2[2];
            #pragma unroll
            for (int u = 0; u < 4; u++) a1[u] = w1p[lane + 32 * u];
            #pragma unroll
            for (int u = 0; u < 4; u++) a2[u] = w2p[lane + 32 * u];
            #pragma unroll
            for (int u = 0; u < 2; u++) e2[u] = wep[lane + 32 * u];

            float s1 = 0.0f, s2 = 0.0f;
            #pragma unroll
            for (int u = 0; u < 4; u++) s1 += dot8h(a1[u], hv, (lane + 32 * u) * 2);
            #pragma unroll
            for (int u = 0; u < 4; u++) s2 += dot8h(a2[u], hv, H / 4 + (lane + 32 * u) * 2);
            #pragma unroll
            for (int u = 0; u < 2; u++) s2 += dot8h(e2[u], hv, 2 * H / 4 + (lane + 32 * u) * 2);
            #pragma unroll
            for (int o = 16; o; o >>= 1) {
                s1 += __shfl_xor_sync(0xffffffffu, s1, o);
                s2 += __shfl_xor_sync(0xffffffffu, s2, o);
            }
            if (lane == 0) {
                red[warp] = s1 + b_ih1[r] + b_hh1[r];
                g_p2[r]   = s2;
            }
            __syncthreads();
            if (tid == 0) {
                const float gi = red[0], gf = red[1], gg = red[2], go = red[3];
                const float cn = sigmoidf_(gf) * __ldcg(&g_c1[j]) + sigmoidf_(gi) * tanhf(gg);
                g_c1[j]       = cn;
                g_h1[pout][j] = sigmoidf_(go) * tanhf(cn);
            }
            __syncthreads();
        }
    };

    // -------- phase-B dependent 2-row task --------
    auto dep2_task = [&](int jb, int pout) {
        {
            const float4* h1p = (const float4*)g_h1[pout];
            float4* s4 = (float4*)sv;
            s4[tid]       = __ldcg(h1p + tid);
            s4[128 + tid] = __ldcg(h1p + 128 + tid);
        }
        __syncthreads();
        const float4* hv = (const float4*)sv;

        #pragma unroll
        for (int half = 0; half < 2; half++) {
            const int j = jb + half * 512;
            const int r = warp * H + j;
            const int4* wr = (const int4*)(g_wih2h + (size_t)r * (H + DW));
            int4 a[4];
            #pragma unroll
            for (int u = 0; u < 4; u++) a[u] = wr[lane + 32 * u];
            float s = 0.0f;
            #pragma unroll
            for (int u = 0; u < 4; u++) s += dot8h(a[u], hv, (lane + 32 * u) * 2);
            #pragma unroll
            for (int o = 16; o; o >>= 1) s += __shfl_xor_sync(0xffffffffu, s, o);
            if (lane == 0) red[warp] = s + __ldcg(&g_p2[r]) + b_ih2[r] + b_hh2[r];
            __syncthreads();
            if (tid == 0) {
                const float gi = red[0], gf = red[1], gg = red[2], go = red[3];
                const float cn = sigmoidf_(gf) * __ldcg(&g_c2[j]) + sigmoidf_(gi) * tanhf(gg);
                g_c2[j]       = cn;
                g_h2[pout][j] = sigmoidf_(go) * tanhf(cn);
            }
            __syncthreads();
        }
    };

    // -------- 32-row logits task: 4 warps x 8 rows --------
    auto logits_task = [&](int s_step, int lt) {
        const int page = s_step & 1;
        const float hs = s_hscale;
        float* out_t = out + (size_t)s_step * VOCAB;
        const int r0 = lt * 32 + warp * 8;

        int acc[8];
        #pragma unroll
        for (int rr = 0; rr < 8; rr++) acc[rr] = 0;
        #pragma unroll
        for (int k0 = 0; k0 < 2; k0++) {
            const int k = lane + 32 * k0;
            const int4 h = qh4[k];
            #pragma unroll
            for (int rr = 0; rr < 8; rr++) {
                const int4 a = *((const int4*)(g_wq + (size_t)(r0 + rr) * (H / 4)) + k);
                acc[rr] = __dp4a(a.x, h.x, acc[rr]);
                acc[rr] = __dp4a(a.y, h.y, acc[rr]);
                acc[rr] = __dp4a(a.z, h.z, acc[rr]);
                acc[rr] = __dp4a(a.w, h.w, acc[rr]);
            }
        }
        #pragma unroll
        for (int rr = 0; rr < 8; rr++) acc[rr] = __reduce_add_sync(0xffffffffu, acc[rr]);
        if (lane == 0) {
            #pragma unroll
            for (int rr = 0; rr < 8; rr++) {
                const float v = g_wscale[r0 + rr] * hs * (float)acc[rr] + b_out[r0 + rr];
                out_t[r0 + rr] = v;
                s_rows[warp * 8 + rr] = v;
            }
        }
        __syncthreads();
        if (tid == 0) {
            float m = s_rows[0];
            #pragma unroll
            for (int u = 1; u < 32; u++) m = fmaxf(m, s_rows[u]);
            float sm = 0.0f;
            #pragma unroll
            for (int u = 0; u < 32; u++) sm += expf(s_rows[u] - m);
            g_lmax[page][lt] = m;
            g_lsum[page][lt] = sm;
        }
        __syncthreads();
    };

    auto combine_task = [&](int s_step) {
        const int page = s_step & 1;
        float m = -3.0e38f, sum = 0.0f;
        const int k0 = tid * 8;
        for (int k = k0; k < k0 + 8 && k < LG_TASKS; k++) {
            const float m2 = __ldcg(&g_lmax[page][k]);
            const float s2 = __ldcg(&g_lsum[page][k]);
            if (m2 > m) { sum = sum * __expf(m - m2) + s2; m = m2; }
            else        { sum += s2 * __expf(m2 - m); }
        }
        sm128[tid] = m; sa128[tid] = sum;
        __syncthreads();
        for (int off = 64; off; off >>= 1) {
            if (tid < off) {
                const float m1 = sm128[tid], sA = sa128[tid];
                const float m2 = sm128[tid + off], sB = sa128[tid + off];
                if (m2 > m1) { sm128[tid] = m2; sa128[tid] = sB + sA * __expf(m1 - m2); }
                else         { sa128[tid] = sA + sB * __expf(m2 - m1); }
            }
            __syncthreads();
        }
        if (tid == 0) g_norm[page] = sm128[0] + logf(sa128[0]);
        __syncthreads();
    };

    auto norm_task = [&](int s_step, int k) {
        const float n = __ldcg(&g_norm[s_step & 1]);
        float4* p = (float4*)(out + (size_t)s_step * VOCAB) + k * 1000;
        for (int i = tid; i < 1000; i += 128) {
            float4 v = __ldcg(p + i);
            v.x -= n; v.y -= n; v.z -= n; v.w -= n;
            p[i] = v;
        }
    };

    auto preamble = [&](int pin, int t) {
        const float4* h2p = (const float4*)g_h2[pin];
        const float4 va = __ldcg(h2p + tid);
        const float4 vb = __ldcg(h2p + 128 + tid);
        float am = fmaxf(fmaxf(fabsf(va.x), fabsf(va.y)), fmaxf(fabsf(va.z), fabsf(va.w)));
        am = fmaxf(am, fmaxf(fmaxf(fabsf(vb.x), fabsf(vb.y)), fmaxf(fabsf(vb.z), fabsf(vb.w))));
        float bm = va.x; int bi = 4 * tid;
        if (va.y > bm) { bm = va.y; bi = 4 * tid + 1; }
        if (va.z > bm) { bm = va.z; bi = 4 * tid + 2; }
        if (va.w > bm) { bm = va.w; bi = 4 * tid + 3; }
        if (vb.x > bm) { bm = vb.x; bi = 512 + 4 * tid; }
        if (vb.y > bm) { bm = vb.y; bi = 512 + 4 * tid + 1; }
        if (vb.z > bm) { bm = vb.z; bi = 512 + 4 * tid + 2; }
        if (vb.w > bm) { bm = vb.w; bi = 512 + 4 * tid + 3; }
        #pragma unroll
        for (int o = 16; o; o >>= 1) {
            const float v2 = __shfl_xor_sync(0xffffffffu, bm, o);
            const int   i2 = __shfl_xor_sync(0xffffffffu, bi, o);
            if (v2 > bm || (v2 == bm && i2 < bi)) { bm = v2; bi = i2; }
            am = fmaxf(am, __shfl_xor_sync(0xffffffffu, am, o));
        }
        if (lane == 0) { s_m[warp] = bm; s_i[warp] = bi; s_a[warp] = am; }
        __syncthreads();
        if (tid == 0) {
            float fm = s_m[0]; int fi = s_i[0];
            float fa = s_a[0];
            #pragma unroll
            for (int u = 1; u < 4; u++) {
                if (s_m[u] > fm || (s_m[u] == fm && s_i[u] < fi)) { fm = s_m[u]; fi = s_i[u]; }
                fa = fmaxf(fa, s_a[u]);
            }
            s_hscale = fa / 127.0f;
            s_inv    = (fa > 0.0f) ? 127.0f / fa : 0.0f;
            s_gidx   = (t == 0) ? 0 : fi;
        }
        __syncthreads();
        const float inv = s_inv;
        ((int*)qh4)[tid]       = pack4(va, inv);
        ((int*)qh4)[128 + tid] = pack4(vb, inv);
        __syncthreads();
    };

    // ================= main decode loop =================
    for (int t = 0; t < NSTEP; t++) {
        const int pin = t & 1, pout = 1 - pin;

        preamble(pin, t);

        // ---- phase A (<=913 tasks, 1 round): fused2 (512) + logits(t-1) 400 + combine(t-2)
        {
            const unsigned nlog = (t >= 1) ? LG_A : 0;
            const unsigned NA = 512u + nlog + ((t >= 2) ? 1u : 0u);
            for (unsigned i = b; i < NA; i += G) {
                if (i < 512u)             fused2_task((int)i, pin, pout);
                else if (i < 512u + nlog) logits_task(t - 1, (int)(i - 512u));
                else                      combine_task(t - 2);
            }
        }
        gbar(G);

        // ---- phase B (<=1120 tasks, 1 round): dep2 (512) + logits(t-1) 600 + norm(t-2)
        {
            const unsigned nlog = (t >= 1) ? (LG_TASKS - LG_A) : 0;
            const unsigned NB = 512u + nlog + ((t >= 2) ? (unsigned)NORM_TASKS : 0u);
            for (unsigned i = b; i < NB; i += G) {
                if (i < 512u)             dep2_task((int)i, pout);
                else if (i < 512u + nlog) logits_task(t - 1, LG_A + (int)(i - 512u));
                else                      norm_task(t - 2, (int)(i - 512u - nlog));
            }
        }
        gbar(G);
    }

    // ================= drain =================
    preamble(NSTEP & 1, NSTEP);
    for (unsigned i = b; i < (unsigned)LG_TASKS + 1u; i += G) {
        if (i < (unsigned)LG_TASKS) logits_task(NSTEP - 1, (int)i);
        else                        combine_task(NSTEP - 2);
    }
    gbar(G);
    for (unsigned i = b; i < (unsigned)NORM_TASKS + 1u; i += G) {
        if (i < (unsigned)NORM_TASKS) norm_task(NSTEP - 2, (int)i);
        else                          combine_task(NSTEP - 1);
    }
    gbar(G);
    for (unsigned i = b; i < (unsigned)NORM_TASKS; i += G) norm_task(NSTEP - 1, (int)i);
}

// ---------------- host driver ----------------
extern "C" void kernel_launch(void* const* d_in, const int* in_sizes, int n_in,
                              void* d_out, int out_size)
{
    const float* vid   = (const float*)d_in[0];
    const float* w_ih1 = (const float*)d_in[1];
    const float* w_hh1 = (const float*)d_in[2];
    const float* b_ih1 = (const float*)d_in[3];
    const float* b_hh1 = (const float*)d_in[4];
    const float* w_ih2 = (const float*)d_in[5];
    const float* w_hh2 = (const float*)d_in[6];
    const float* b_ih2 = (const float*)d_in[7];
    const float* b_hh2 = (const float*)d_in[8];
    const float* emb   = (const float*)d_in[9];
    const float* w_out = (const float*)d_in[10];
    const float* b_out = (const float*)d_in[11];
    float* out = (float*)d_out;

    (void)in_sizes; (void)n_in; (void)out_size;

    static cudaStream_t sB = nullptr;
    static cudaEvent_t evStart = nullptr, evB = nullptr;
    static int smCount = 0;
    if (!sB) {
        cudaStreamCreateWithFlags(&sB, cudaStreamNonBlocking);
        cudaEventCreateWithFlags(&evStart, cudaEventDisableTiming);
        cudaEventCreateWithFlags(&evB,     cudaEventDisableTiming);
        cudaDeviceGetAttribute(&smCount, cudaDevAttrMultiProcessorCount, 0);
    }
    const unsigned G = (unsigned)smCount * 8u;   // divisible by 32 on GB300

    k_init<<<1, 1>>>();

    cudaEventRecord(evStart, 0);
    cudaStreamWaitEvent(sB, evStart, 0);
    k_quant_w<<<VOCAB / 32, 256, 0, sB>>>(w_out);
    k_cvt<<<2048, 256, 0, sB>>>(w_hh1, w_ih2, w_hh2);
    cudaEventRecord(evB, sB);

    k_lstm1_enc<<<H, 128>>>(w_ih1, vid, b_ih1, b_hh1);
    k_l2enc<<<H, 128>>>(w_ih2, b_ih2, b_hh2);

    cudaStreamWaitEvent(0, evB, 0);
    k_decode<<<G, 128>>>(b_ih1, b_hh1, b_ih2, b_hh2, emb, b_out, out, G);
}

// round 16
// speedup vs baseline: 1.1382x; 1.0302x over previous
#include <cuda_runtime.h>
#include <cuda_fp16.h>
#include <cstddef>
#include <cstdint>

#define H       1024
#define DV      4096
#define DW      512
#define VOCAB   32000
#define NSTEP   39      // MAX_LEN - 1
#define LG_TASKS 1000   // logits tasks per step, 32 rows each
#define NORM_TASKS 8

// ---------------- persistent device state ----------------
__device__ float g_h1[2][H];
__device__ float g_c1[H];
__device__ float g_h2[2][H];
__device__ float g_c2[H];
__device__ float g_p2[4 * H];

__device__ __align__(16) __half g_whh1h[4 * H * H];
__device__ __align__(16) __half g_wih2h[4 * H * (H + DW)];
__device__ __align__(16) __half g_whh2h[4 * H * H];

__device__ int   g_wq[VOCAB * (H / 4)];
__device__ float g_wscale[VOCAB];

__device__ float g_lmax[2][LG_TASKS];
__device__ float g_lsum[2][LG_TASKS];
__device__ float g_norm[2];

__device__ unsigned g_cnt[32];
__device__ unsigned g_mst;
__device__ unsigned g_gen;
__device__ unsigned g_h1cnt;   // monotonic: 512 per step when h1 fully written

__device__ __forceinline__ float sigmoidf_(float x) { return 1.0f / (1.0f + expf(-x)); }

// ---------------- hierarchical grid barrier (32 | G) ----------------
__device__ __forceinline__ void gbar(unsigned G)
{
    __syncthreads();
    if (threadIdx.x == 0) {
        __threadfence();
        const unsigned gen = *(volatile unsigned*)&g_gen;
        const unsigned sub = blockIdx.x & 31u;
        const unsigned subTarget = G >> 5;
        if (atomicAdd(&g_cnt[sub], 1u) == subTarget - 1u) {
            atomicExch(&g_cnt[sub], 0u);
            if (atomicAdd(&g_mst, 1u) == 31u) {
                atomicExch(&g_mst, 0u);
                __threadfence();
                atomicAdd(&g_gen, 1u);
            } else {
                while (*(volatile unsigned*)&g_gen == gen) __nanosleep(32);
            }
        } else {
            while (*(volatile unsigned*)&g_gen == gen) __nanosleep(64);
        }
        __threadfence();
    }
    __syncthreads();
}

// ---------------- one-time prep: init counters + int8 w_out + fp16 recurrence ----------------
// blocks [0,1000): quantize w_out (32 rows each); blocks [1000,3048): fp16 convert slice.
__global__ void k_prep(const float* __restrict__ w_out,
                       const float* __restrict__ w_hh1, const float* __restrict__ w_ih2,
                       const float* __restrict__ w_hh2)
{
    if (blockIdx.x == 0 && threadIdx.x == 0) {
        for (int i = 0; i < 32; i++) g_cnt[i] = 0;
        g_mst = 0; g_gen = 0; g_h1cnt = 0;
    }
    if (blockIdx.x < 1000) {
        const int warp = threadIdx.x >> 5;
        const int lane = threadIdx.x & 31;
        const int row0 = blockIdx.x * 32 + warp * 4;
        for (int rr = 0; rr < 4; rr++) {
            const int row = row0 + rr;
            const float4* wr = (const float4*)(w_out + (size_t)row * H);
            float4 v[8];
            float m = 0.0f;
            #pragma unroll
            for (int i = 0; i < 8; i++) {
                v[i] = wr[lane + 32 * i];
                m = fmaxf(m, fmaxf(fmaxf(fabsf(v[i].x), fabsf(v[i].y)),
                                   fmaxf(fabsf(v[i].z), fabsf(v[i].w))));
            }
            #pragma unroll
            for (int o = 16; o; o >>= 1) m = fmaxf(m, __shfl_xor_sync(0xffffffffu, m, o));
            const float inv = (m > 0.0f) ? 127.0f / m : 0.0f;
            #pragma unroll
            for (int i = 0; i < 8; i++) {
                const int a = (int)rintf(v[i].x * inv);
                const int b = (int)rintf(v[i].y * inv);
                const int c = (int)rintf(v[i].z * inv);
                const int d = (int)rintf(v[i].w * inv);
                g_wq[row * (H / 4) + lane + 32 * i] =
                    (a & 0xFF) | ((b & 0xFF) << 8) | ((c & 0xFF) << 16) | ((d & 0xFF) << 24);
            }
            if (lane == 0) g_wscale[row] = m / 127.0f;
        }
    } else {
        const int stride = 2048 * 256;
        const int t0 = (blockIdx.x - 1000) * 256 + threadIdx.x;
        const int n1 = 4 * H * H / 2, n2 = 4 * H * (H + DW) / 2;
        const float2* s1 = (const float2*)w_hh1;  __half2* d1 = (__half2*)g_whh1h;
        const float2* s2 = (const float2*)w_ih2;  __half2* d2 = (__half2*)g_wih2h;
        const float2* s3 = (const float2*)w_hh2;  __half2* d3 = (__half2*)g_whh2h;
        for (int i = t0; i < n1; i += stride) d1[i] = __float22half2_rn(s1[i]);
        for (int i = t0; i < n2; i += stride) d2[i] = __float22half2_rn(s2[i]);
        for (int i = t0; i < n1; i += stride) d3[i] = __float22half2_rn(s3[i]);
    }
}

// ---------------- encode kernels (fp32 weights) ----------------
__global__ void k_lstm1_enc(const float* __restrict__ w_ih, const float* __restrict__ x,
                            const float* __restrict__ b_ih, const float* __restrict__ b_hh)
{
    __shared__ float sx[DV];
    __shared__ float red[4];
    const int j = blockIdx.x, tid = threadIdx.x, warp = tid >> 5, lane = tid & 31;

    for (int i = tid; i < DV; i += 128) sx[i] = x[i];
    __syncthreads();

    const int r = warp * H + j;
    const float4* wr = (const float4*)(w_ih + (size_t)r * DV);
    const float4* xv = (const float4*)sx;
    float s = 0.0f;
    #pragma unroll
    for (int k0 = 0; k0 < DV / 4; k0 += 256) {
        float4 a[8];
        #pragma unroll
        for (int u = 0; u < 8; u++) a[u] = wr[k0 + lane + 32 * u];
        #pragma unroll
        for (int u = 0; u < 8; u++) {
            const float4 b = xv[k0 + lane + 32 * u];
            s += a[u].x * b.x + a[u].y * b.y + a[u].z * b.z + a[u].w * b.w;
        }
    }
    #pragma unroll
    for (int o = 16; o; o >>= 1) s += __shfl_xor_sync(0xffffffffu, s, o);
    if (lane == 0) red[warp] = s + b_ih[r] + b_hh[r];
    __syncthreads();

    if (tid == 0) {
        const float gi = red[0], gf = red[1], gg = red[2], go = red[3];
        const float cn = sigmoidf_(gi) * tanhf(gg);
        g_c1[j]    = cn;
        g_h1[0][j] = sigmoidf_(go) * tanhf(cn);
    }
}

__global__ void k_l2enc(const float* __restrict__ w_ih,
                        const float* __restrict__ b_ih, const float* __restrict__ b_hh)
{
    __shared__ float sh[H];
    __shared__ float red[4];
    const int j = blockIdx.x, tid = threadIdx.x, warp = tid >> 5, lane = tid & 31;

    for (int i = tid; i < H; i += 128) sh[i] = g_h1[0][i];
    __syncthreads();

    const int r = warp * H + j;
    const float4* wr = (const float4*)(w_ih + (size_t)r * (H + DW));
    const float4* hv = (const float4*)sh;
    float4 a[8];
    #pragma unroll
    for (int u = 0; u < 8; u++) a[u] = wr[lane + 32 * u];
    float s = 0.0f;
    #pragma unroll
    for (int u = 0; u < 8; u++) {
        const float4 b = hv[lane + 32 * u];
        s += a[u].x * b.x + a[u].y * b.y + a[u].z * b.z + a[u].w * b.w;
    }
    #pragma unroll
    for (int o = 16; o; o >>= 1) s += __shfl_xor_sync(0xffffffffu, s, o);
    if (lane == 0) red[warp] = s + b_ih[r] + b_hh[r];
    __syncthreads();

    if (tid == 0) {
        const float gi = red[0], gf = red[1], gg = red[2], go = red[3];
        const float cn = sigmoidf_(gi) * tanhf(gg);
        g_c2[j]    = cn;
        g_h2[0][j] = sigmoidf_(go) * tanhf(cn);
    }
}

// ---------------- helpers ----------------
__device__ __forceinline__ int pack4(float4 v, float inv)
{
    const int a = (int)rintf(v.x * inv);
    const int b = (int)rintf(v.y * inv);
    const int c = (int)rintf(v.z * inv);
    const int d = (int)rintf(v.w * inv);
    return (a & 0xFF) | ((b & 0xFF) << 8) | ((c & 0xFF) << 16) | ((d & 0xFF) << 24);
}

__device__ __forceinline__ float dot8h(int4 p, const float4* hv4, int pairIdx)
{
    const float4 hA = hv4[pairIdx];
    const float4 hB = hv4[pairIdx + 1];
    const float2 w0 = __half22float2(*(__half2*)&p.x);
    const float2 w1 = __half22float2(*(__half2*)&p.y);
    const float2 w2 = __half22float2(*(__half2*)&p.z);
    const float2 w3 = __half22float2(*(__half2*)&p.w);
    return w0.x * hA.x + w0.y * hA.y + w1.x * hA.z + w1.y * hA.w
         + w2.x * hB.x + w2.y * hB.y + w3.x * hB.z + w3.y * hB.w;
}

// ---------------- persistent decode kernel ----------------
__global__ void __launch_bounds__(128, 8)
k_decode(const float* __restrict__ b_ih1, const float* __restrict__ b_hh1,
         const float* __restrict__ b_ih2, const float* __restrict__ b_hh2,
         const float* __restrict__ emb,  const float* __restrict__ b_out,
         float* __restrict__ out, unsigned G)
{
    __shared__ float sv[2 * H + DW];
    __shared__ int4  qh4[H / 16];
    __shared__ float red[4];
    __shared__ float s_m[4];
    __shared__ int   s_i[4];
    __shared__ float s_a[4];
    __shared__ float sm128[128];
    __shared__ float sa128[128];
    __shared__ float s_rows[32];
    __shared__ float s_hscale, s_inv;
    __shared__ int   s_gidx;

    const unsigned b   = blockIdx.x;
    const int tid  = threadIdx.x;
    const int warp = tid >> 5;
    const int lane = tid & 31;

    // -------- fused 2-row recurrence producer (rows jb, jb+512): lstm1 + lstm2-independent --
    auto fused2_task = [&](int jb, int pin, int pout) {
        {
            const float4* h1p = (const float4*)g_h1[pin];
            const float4* h2p = (const float4*)g_h2[pin];
            float4* s4 = (float4*)sv;
            s4[tid]       = __ldcg(h1p + tid);
            s4[128 + tid] = __ldcg(h1p + 128 + tid);
            s4[256 + tid] = __ldcg(h2p + tid);
            s4[384 + tid] = __ldcg(h2p + 128 + tid);
            const float4* ev = (const float4*)(emb + (size_t)s_gidx * DW);
            s4[512 + tid] = ev[tid];
        }
        __syncthreads();
        const float4* hv = (const float4*)sv;

        #pragma unroll
        for (int half = 0; half < 2; half++) {
            const int j = jb + half * 512;
            const int r = warp * H + j;
            const int4* w1p = (const int4*)(g_whh1h + (size_t)r * H);
            const int4* w2p = (const int4*)(g_whh2h + (size_t)r * H);
            const int4* wep = (const int4*)(g_wih2h + (size_t)r * (H + DW) + H);
            int4 a1[4], a2[4], e2[2];
            #pragma unroll
            for (int u = 0; u < 4; u++) a1[u] = w1p[lane + 32 * u];
            #pragma unroll
            for (int u = 0; u < 4; u++) a2[u] = w2p[lane + 32 * u];
            #pragma unroll
            for (int u = 0; u < 2; u++) e2[u] = wep[lane + 32 * u];

            float s1 = 0.0f, s2 = 0.0f;
            #pragma unroll
            for (int u = 0; u < 4; u++) s1 += dot8h(a1[u], hv, (lane + 32 * u) * 2);
            #pragma unroll
            for (int u = 0; u < 4; u++) s2 += dot8h(a2[u], hv, H / 4 + (lane + 32 * u) * 2);
            #pragma unroll
            for (int u = 0; u < 2; u++) s2 += dot8h(e2[u], hv, 2 * H / 4 + (lane + 32 * u) * 2);
            #pragma unroll
            for (int o = 16; o; o >>= 1) {
                s1 += __shfl_xor_sync(0xffffffffu, s1, o);
                s2 += __shfl_xor_sync(0xffffffffu, s2, o);
            }
            if (lane == 0) {
                red[warp] = s1 + b_ih1[r] + b_hh1[r];
                g_p2[r]   = s2;
            }
            __syncthreads();
            if (tid == 0) {
                const float gi = red[0], gf = red[1], gg = red[2], go = red[3];
                const float cn = sigmoidf_(gf) * __ldcg(&g_c1[j]) + sigmoidf_(gi) * tanhf(gg);
                g_c1[j]       = cn;
                g_h1[pout][j] = sigmoidf_(go) * tanhf(cn);
                if (half == 1) {           // release: both rows of h1 published
                    __threadfence();
                    atomicAdd(&g_h1cnt, 1u);
                }
            }
            __syncthreads();
        }
    };

    // -------- dependent 2-row consumer: waits for all 512 fused2 producers of this step ----
    auto dep2_task = [&](int jb, int pout, int t) {
        if (tid == 0) {
            const unsigned target = 512u * (unsigned)(t + 1);
            while (*(volatile unsigned*)&g_h1cnt < target) __nanosleep(128);
            __threadfence();   // acquire
        }
        __syncthreads();
        {
            const float4* h1p = (const float4*)g_h1[pout];
            float4* s4 = (float4*)sv;
            s4[tid]       = __ldcg(h1p + tid);
            s4[128 + tid] = __ldcg(h1p + 128 + tid);
        }
        __syncthreads();
        const float4* hv = (const float4*)sv;

        #pragma unroll
        for (int half = 0; half < 2; half++) {
            const int j = jb + half * 512;
            const int r = warp * H + j;
            const int4* wr = (const int4*)(g_wih2h + (size_t)r * (H + DW));
            int4 a[4];
            #pragma unroll
            for (int u = 0; u < 4; u++) a[u] = wr[lane + 32 * u];
            float s = 0.0f;
            #pragma unroll
            for (int u = 0; u < 4; u++) s += dot8h(a[u], hv, (lane + 32 * u) * 2);
            #pragma unroll
            for (int o = 16; o; o >>= 1) s += __shfl_xor_sync(0xffffffffu, s, o);
            if (lane == 0) red[warp] = s + __ldcg(&g_p2[r]) + b_ih2[r] + b_hh2[r];
            __syncthreads();
            if (tid == 0) {
                const float gi = red[0], gf = red[1], gg = red[2], go = red[3];
                const float cn = sigmoidf_(gf) * __ldcg(&g_c2[j]) + sigmoidf_(gi) * tanhf(gg);
                g_c2[j]       = cn;
                g_h2[pout][j] = sigmoidf_(go) * tanhf(cn);
            }
            __syncthreads();
        }
    };

    // -------- 32-row logits task --------
    auto logits_task = [&](int s_step, int lt) {
        const int page = s_step & 1;
        const float hs = s_hscale;
        float* out_t = out + (size_t)s_step * VOCAB;
        const int r0 = lt * 32 + warp * 8;

        int acc[8];
        #pragma unroll
        for (int rr = 0; rr < 8; rr++) acc[rr] = 0;
        #pragma unroll
        for (int k0 = 0; k0 < 2; k0++) {
            const int k = lane + 32 * k0;
            const int4 h = qh4[k];
            #pragma unroll
            for (int rr = 0; rr < 8; rr++) {
                const int4 a = *((const int4*)(g_wq + (size_t)(r0 + rr) * (H / 4)) + k);
                acc[rr] = __dp4a(a.x, h.x, acc[rr]);
                acc[rr] = __dp4a(a.y, h.y, acc[rr]);
                acc[rr] = __dp4a(a.z, h.z, acc[rr]);
                acc[rr] = __dp4a(a.w, h.w, acc[rr]);
            }
        }
        #pragma unroll
        for (int rr = 0; rr < 8; rr++) acc[rr] = __reduce_add_sync(0xffffffffu, acc[rr]);
        if (lane == 0) {
            #pragma unroll
            for (int rr = 0; rr < 8; rr++) {
                const float v = g_wscale[r0 + rr] * hs * (float)acc[rr] + b_out[r0 + rr];
                out_t[r0 + rr] = v;
                s_rows[warp * 8 + rr] = v;
            }
        }
        __syncthreads();
        if (tid == 0) {
            float m = s_rows[0];
            #pragma unroll
            for (int u = 1; u < 32; u++) m = fmaxf(m, s_rows[u]);
            float sm = 0.0f;
            #pragma unroll
            for (int u = 0; u < 32; u++) sm += expf(s_rows[u] - m);
            g_lmax[page][lt] = m;
            g_lsum[page][lt] = sm;
        }
        __syncthreads();
    };

    auto combine_task = [&](int s_step) {
        const int page = s_step & 1;
        float m = -3.0e38f, sum = 0.0f;
        const int k0 = tid * 8;
        for (int k = k0; k < k0 + 8 && k < LG_TASKS; k++) {
            const float m2 = __ldcg(&g_lmax[page][k]);
            const float s2 = __ldcg(&g_lsum[page][k]);
            if (m2 > m) { sum = sum * __expf(m - m2) + s2; m = m2; }
            else        { sum += s2 * __expf(m2 - m); }
        }
        sm128[tid] = m; sa128[tid] = sum;
        __syncthreads();
        for (int off = 64; off; off >>= 1) {
            if (tid < off) {
                const float m1 = sm128[tid], sA = sa128[tid];
                const float m2 = sm128[tid + off], sB = sa128[tid + off];
                if (m2 > m1) { sm128[tid] = m2; sa128[tid] = sB + sA * __expf(m1 - m2); }
                else         { sa128[tid] = sA + sB * __expf(m2 - m1); }
            }
            __syncthreads();
        }
        if (tid == 0) g_norm[page] = sm128[0] + logf(sa128[0]);
        __syncthreads();
    };

    auto norm_task = [&](int s_step, int k) {
        const float n = __ldcg(&g_norm[s_step & 1]);
        float4* p = (float4*)(out + (size_t)s_step * VOCAB) + k * 1000;
        for (int i = tid; i < 1000; i += 128) {
            float4 v = __ldcg(p + i);
            v.x -= n; v.y -= n; v.z -= n; v.w -= n;
            p[i] = v;
        }
    };

    auto preamble = [&](int pin, int t) {
        const float4* h2p = (const float4*)g_h2[pin];
        const float4 va = __ldcg(h2p + tid);
        const float4 vb = __ldcg(h2p + 128 + tid);
        float am = fmaxf(fmaxf(fabsf(va.x), fabsf(va.y)), fmaxf(fabsf(va.z), fabsf(va.w)));
        am = fmaxf(am, fmaxf(fmaxf(fabsf(vb.x), fabsf(vb.y)), fmaxf(fabsf(vb.z), fabsf(vb.w))));
        float bm = va.x; int bi = 4 * tid;
        if (va.y > bm) { bm = va.y; bi = 4 * tid + 1; }
        if (va.z > bm) { bm = va.z; bi = 4 * tid + 2; }
        if (va.w > bm) { bm = va.w; bi = 4 * tid + 3; }
        if (vb.x > bm) { bm = vb.x; bi = 512 + 4 * tid; }
        if (vb.y > bm) { bm = vb.y; bi = 512 + 4 * tid + 1; }
        if (vb.z > bm) { bm = vb.z; bi = 512 + 4 * tid + 2; }
        if (vb.w > bm) { bm = vb.w; bi = 512 + 4 * tid + 3; }
        #pragma unroll
        for (int o = 16; o; o >>= 1) {
            const float v2 = __shfl_xor_sync(0xffffffffu, bm, o);
            const int   i2 = __shfl_xor_sync(0xffffffffu, bi, o);
            if (v2 > bm || (v2 == bm && i2 < bi)) { bm = v2; bi = i2; }
            am = fmaxf(am, __shfl_xor_sync(0xffffffffu, am, o));
        }
        if (lane == 0) { s_m[warp] = bm; s_i[warp] = bi; s_a[warp] = am; }
        __syncthreads();
        if (tid == 0) {
            float fm = s_m[0]; int fi = s_i[0];
            float fa = s_a[0];
            #pragma unroll
            for (int u = 1; u < 4; u++) {
                if (s_m[u] > fm || (s_m[u] == fm && s_i[u] < fi)) { fm = s_m[u]; fi = s_i[u]; }
                fa = fmaxf(fa, s_a[u]);
            }
            s_hscale = fa / 127.0f;
            s_inv    = (fa > 0.0f) ? 127.0f / fa : 0.0f;
            s_gidx   = (t == 0) ? 0 : fi;
        }
        __syncthreads();
        const float inv = s_inv;
        ((int*)qh4)[tid]       = pack4(va, inv);
        ((int*)qh4)[128 + tid] = pack4(vb, inv);
        __syncthreads();
    };

    // ================= main decode loop: ONE merged pool + ONE barrier per step ============
    for (int t = 0; t < NSTEP; t++) {
        const int pin = t & 1, pout = 1 - pin;

        preamble(pin, t);

        const unsigned nlog = (t >= 1) ? (unsigned)LG_TASKS : 0u;
        const unsigned ncmb = (t >= 2) ? 1u : 0u;
        const unsigned nnrm = (t >= 3) ? (unsigned)NORM_TASKS : 0u;
        const unsigned depBase = 512u + nlog + ncmb + nnrm;
        const unsigned NT = depBase + 512u;

        for (unsigned i = b; i < NT; i += G) {
            if (i < 512u)                     fused2_task((int)i, pin, pout);
            else if (i < 512u + nlog)         logits_task(t - 1, (int)(i - 512u));
            else if (i < 512u + nlog + ncmb)  combine_task(t - 2);
            else if (i < depBase)             norm_task(t - 3, (int)(i - 512u - nlog - ncmb));
            else                              dep2_task((int)(i - depBase), pout, t);
        }
        gbar(G);
    }

    // ================= drain =================
    // D1: logits(38) + combine(37) + norm(36)
    preamble(NSTEP & 1, NSTEP);
    for (unsigned i = b; i < (unsigned)LG_TASKS + 1u + (unsigned)NORM_TASKS; i += G) {
        if (i < (unsigned)LG_TASKS)           logits_task(NSTEP - 1, (int)i);
        else if (i < (unsigned)LG_TASKS + 1u) combine_task(NSTEP - 2);
        else                                  norm_task(NSTEP - 3, (int)(i - LG_TASKS - 1u));
    }
    gbar(G);
    // D2: combine(38) + norm(37)
    for (unsigned i = b; i < 1u + (unsigned)NORM_TASKS; i += G) {
        if (i < 1u) combine_task(NSTEP - 1);
        else        norm_task(NSTEP - 2, (int)(i - 1u));
    }
    gbar(G);
    // D3: norm(38)
    for (unsigned i = b; i < (unsigned)NORM_TASKS; i += G) norm_task(NSTEP - 1, (int)i);
}

// ---------------- host driver ----------------
extern "C" void kernel_launch(void* const* d_in, const int* in_sizes, int n_in,
                              void* d_out, int out_size)
{
    const float* vid   = (const float*)d_in[0];
    const float* w_ih1 = (const float*)d_in[1];
    const float* w_hh1 = (const float*)d_in[2];
    const float* b_ih1 = (const float*)d_in[3];
    const float* b_hh1 = (const float*)d_in[4];
    const float* w_ih2 = (const float*)d_in[5];
    const float* w_hh2 = (const float*)d_in[6];
    const float* b_ih2 = (const float*)d_in[7];
    const float* b_hh2 = (const float*)d_in[8];
    const float* emb   = (const float*)d_in[9];
    const float* w_out = (const float*)d_in[10];
    const float* b_out = (const float*)d_in[11];
    float* out = (float*)d_out;

    (void)in_sizes; (void)n_in; (void)out_size;

    static cudaStream_t sB = nullptr;
    static cudaEvent_t evStart = nullptr, evB = nullptr;
    static int smCount = 0;
    if (!sB) {
        cudaStreamCreateWithFlags(&sB, cudaStreamNonBlocking);
        cudaEventCreateWithFlags(&evStart, cudaEventDisableTiming);
        cudaEventCreateWithFlags(&evB,     cudaEventDisableTiming);
        cudaDeviceGetAttribute(&smCount, cudaDevAttrMultiProcessorCount, 0);
    }
    const unsigned G = (unsigned)smCount * 8u;   // divisible by 32 on GB300

    // stream B: one merged prep kernel (counters + int8 w_out + fp16 recurrence)
    cudaEventRecord(evStart, 0);
    cudaStreamWaitEvent(sB, evStart, 0);
    k_prep<<<3048, 256, 0, sB>>>(w_out, w_hh1, w_ih2, w_hh2);
    cudaEventRecord(evB, sB);

    // main: encode (fp32 weights)
    k_lstm1_enc<<<H, 128>>>(w_ih1, vid, b_ih1, b_hh1);
    k_l2enc<<<H, 128>>>(w_ih2, b_ih2, b_hh2);

    cudaStreamWaitEvent(0, evB, 0);
    k_decode<<<G, 128>>>(b_ih1, b_hh1, b_ih2, b_hh2, emb, b_out, out, G);
}

// round 17
// speedup vs baseline: 1.1986x; 1.0531x over previous
#include <cuda_runtime.h>
#include <cuda_fp16.h>
#include <cstddef>
#include <cstdint>

#define H       1024
#define DV      4096
#define DW      512
#define VOCAB   32000
#define NSTEP   39       // MAX_LEN - 1
#define LG_WT   4000     // warp-level logits tasks per step, 8 rows each
#define NORM_TASKS 8

// ---------------- persistent device state ----------------
__device__ float g_h1[2][H];
__device__ float g_c1[H];
__device__ float g_h2[2][H];
__device__ float g_c2[H];
__device__ float g_p2[4 * H];

__device__ __align__(16) __half g_whh1h[4 * H * H];
__device__ __align__(16) __half g_wih2h[4 * H * (H + DW)];
__device__ __align__(16) __half g_whh2h[4 * H * H];

__device__ int   g_wq[VOCAB * (H / 4)];
__device__ float g_wscale[VOCAB];

__device__ float g_lmax[2][LG_WT];
__device__ float g_lsum[2][LG_WT];
__device__ float g_norm[2];

__device__ unsigned g_cnt[32];
__device__ unsigned g_mst;
__device__ unsigned g_gen;
__device__ unsigned g_h1cnt;

__device__ __forceinline__ float sigmoidf_(float x) { return 1.0f / (1.0f + expf(-x)); }

// ---------------- hierarchical grid barrier (32 | G) ----------------
__device__ __forceinline__ void gbar(unsigned G)
{
    __syncthreads();
    if (threadIdx.x == 0) {
        __threadfence();
        const unsigned gen = *(volatile unsigned*)&g_gen;
        const unsigned sub = blockIdx.x & 31u;
        const unsigned subTarget = G >> 5;
        if (atomicAdd(&g_cnt[sub], 1u) == subTarget - 1u) {
            atomicExch(&g_cnt[sub], 0u);
            if (atomicAdd(&g_mst, 1u) == 31u) {
                atomicExch(&g_mst, 0u);
                __threadfence();
                atomicAdd(&g_gen, 1u);
            } else {
                while (*(volatile unsigned*)&g_gen == gen) __nanosleep(32);
            }
        } else {
            while (*(volatile unsigned*)&g_gen == gen) __nanosleep(64);
        }
        __threadfence();
    }
    __syncthreads();
}

// ---------------- one-time prep ----------------
__global__ void k_prep(const float* __restrict__ w_out,
                       const float* __restrict__ w_hh1, const float* __restrict__ w_ih2,
                       const float* __restrict__ w_hh2)
{
    if (blockIdx.x == 0 && threadIdx.x == 0) {
        for (int i = 0; i < 32; i++) g_cnt[i] = 0;
        g_mst = 0; g_gen = 0; g_h1cnt = 0;
    }
    if (blockIdx.x < 1000) {
        const int warp = threadIdx.x >> 5;
        const int lane = threadIdx.x & 31;
        const int row0 = blockIdx.x * 32 + warp * 4;
        for (int rr = 0; rr < 4; rr++) {
            const int row = row0 + rr;
            const float4* wr = (const float4*)(w_out + (size_t)row * H);
            float4 v[8];
            float m = 0.0f;
            #pragma unroll
            for (int i = 0; i < 8; i++) {
                v[i] = wr[lane + 32 * i];
                m = fmaxf(m, fmaxf(fmaxf(fabsf(v[i].x), fabsf(v[i].y)),
                                   fmaxf(fabsf(v[i].z), fabsf(v[i].w))));
            }
            #pragma unroll
            for (int o = 16; o; o >>= 1) m = fmaxf(m, __shfl_xor_sync(0xffffffffu, m, o));
            const float inv = (m > 0.0f) ? 127.0f / m : 0.0f;
            #pragma unroll
            for (int i = 0; i < 8; i++) {
                const int a = (int)rintf(v[i].x * inv);
                const int b = (int)rintf(v[i].y * inv);
                const int c = (int)rintf(v[i].z * inv);
                const int d = (int)rintf(v[i].w * inv);
                g_wq[row * (H / 4) + lane + 32 * i] =
                    (a & 0xFF) | ((b & 0xFF) << 8) | ((c & 0xFF) << 16) | ((d & 0xFF) << 24);
            }
            if (lane == 0) g_wscale[row] = m / 127.0f;
        }
    } else {
        const int stride = 2048 * 256;
        const int t0 = (blockIdx.x - 1000) * 256 + threadIdx.x;
        const int n1 = 4 * H * H / 2, n2 = 4 * H * (H + DW) / 2;
        const float2* s1 = (const float2*)w_hh1;  __half2* d1 = (__half2*)g_whh1h;
        const float2* s2 = (const float2*)w_ih2;  __half2* d2 = (__half2*)g_wih2h;
        const float2* s3 = (const float2*)w_hh2;  __half2* d3 = (__half2*)g_whh2h;
        for (int i = t0; i < n1; i += stride) d1[i] = __float22half2_rn(s1[i]);
        for (int i = t0; i < n2; i += stride) d2[i] = __float22half2_rn(s2[i]);
        for (int i = t0; i < n1; i += stride) d3[i] = __float22half2_rn(s3[i]);
    }
}

// ---------------- encode kernels (fp32 weights) ----------------
__global__ void k_lstm1_enc(const float* __restrict__ w_ih, const float* __restrict__ x,
                            const float* __restrict__ b_ih, const float* __restrict__ b_hh)
{
    __shared__ float sx[DV];
    __shared__ float red[4];
    const int j = blockIdx.x, tid = threadIdx.x, warp = tid >> 5, lane = tid & 31;

    for (int i = tid; i < DV; i += 128) sx[i] = x[i];
    __syncthreads();

    const int r = warp * H + j;
    const float4* wr = (const float4*)(w_ih + (size_t)r * DV);
    const float4* xv = (const float4*)sx;
    float s = 0.0f;
    #pragma unroll
    for (int k0 = 0; k0 < DV / 4; k0 += 256) {
        float4 a[8];
        #pragma unroll
        for (int u = 0; u < 8; u++) a[u] = wr[k0 + lane + 32 * u];
        #pragma unroll
        for (int u = 0; u < 8; u++) {
            const float4 b = xv[k0 + lane + 32 * u];
            s += a[u].x * b.x + a[u].y * b.y + a[u].z * b.z + a[u].w * b.w;
        }
    }
    #pragma unroll
    for (int o = 16; o; o >>= 1) s += __shfl_xor_sync(0xffffffffu, s, o);
    if (lane == 0) red[warp] = s + b_ih[r] + b_hh[r];
    __syncthreads();

    if (tid == 0) {
        const float gi = red[0], gf = red[1], gg = red[2], go = red[3];
        const float cn = sigmoidf_(gi) * tanhf(gg);
        g_c1[j]    = cn;
        g_h1[0][j] = sigmoidf_(go) * tanhf(cn);
    }
}

__global__ void k_l2enc(const float* __restrict__ w_ih,
                        const float* __restrict__ b_ih, const float* __restrict__ b_hh)
{
    __shared__ float sh[H];
    __shared__ float red[4];
    const int j = blockIdx.x, tid = threadIdx.x, warp = tid >> 5, lane = tid & 31;

    for (int i = tid; i < H; i += 128) sh[i] = g_h1[0][i];
    __syncthreads();

    const int r = warp * H + j;
    const float4* wr = (const float4*)(w_ih + (size_t)r * (H + DW));
    const float4* hv = (const float4*)sh;
    float4 a[8];
    #pragma unroll
    for (int u = 0; u < 8; u++) a[u] = wr[lane + 32 * u];
    float s = 0.0f;
    #pragma unroll
    for (int u = 0; u < 8; u++) {
        const float4 b = hv[lane + 32 * u];
        s += a[u].x * b.x + a[u].y * b.y + a[u].z * b.z + a[u].w * b.w;
    }
    #pragma unroll
    for (int o = 16; o; o >>= 1) s += __shfl_xor_sync(0xffffffffu, s, o);
    if (lane == 0) red[warp] = s + b_ih[r] + b_hh[r];
    __syncthreads();

    if (tid == 0) {
        const float gi = red[0], gf = red[1], gg = red[2], go = red[3];
        const float cn = sigmoidf_(gi) * tanhf(gg);
        g_c2[j]    = cn;
        g_h2[0][j] = sigmoidf_(go) * tanhf(cn);
    }
}

// ---------------- helpers ----------------
__device__ __forceinline__ int pack4(float4 v, float inv)
{
    const int a = (int)rintf(v.x * inv);
    const int b = (int)rintf(v.y * inv);
    const int c = (int)rintf(v.z * inv);
    const int d = (int)rintf(v.w * inv);
    return (a & 0xFF) | ((b & 0xFF) << 8) | ((c & 0xFF) << 16) | ((d & 0xFF) << 24);
}

__device__ __forceinline__ float dot8h(int4 p, const float4* hv4, int pairIdx)
{
    const float4 hA = hv4[pairIdx];
    const float4 hB = hv4[pairIdx + 1];
    const float2 w0 = __half22float2(*(__half2*)&p.x);
    const float2 w1 = __half22float2(*(__half2*)&p.y);
    const float2 w2 = __half22float2(*(__half2*)&p.z);
    const float2 w3 = __half22float2(*(__half2*)&p.w);
    return w0.x * hA.x + w0.y * hA.y + w1.x * hA.z + w1.y * hA.w
         + w2.x * hB.x + w2.y * hB.y + w3.x * hB.z + w3.y * hB.w;
}

// ---------------- persistent decode kernel ----------------
__global__ void __launch_bounds__(128, 8)
k_decode(const float* __restrict__ b_ih1, const float* __restrict__ b_hh1,
         const float* __restrict__ b_ih2, const float* __restrict__ b_hh2,
         const float* __restrict__ emb,  const float* __restrict__ b_out,
         float* __restrict__ out, unsigned G)
{
    __shared__ float sv[2 * H + DW];
    __shared__ int4  qh4[H / 16];
    __shared__ float red[4];
    __shared__ float s_m[4];
    __shared__ int   s_i[4];
    __shared__ float s_a[4];
    __shared__ float sm128[128];
    __shared__ float sa128[128];
    __shared__ float s_hscale, s_inv;
    __shared__ int   s_gidx;

    const unsigned b   = blockIdx.x;
    const int tid  = threadIdx.x;
    const int warp = tid >> 5;
    const int lane = tid & 31;
    const int wgid = (int)b * 4 + warp;      // global warp id

    // -------- fused 2-row recurrence producer --------
    auto fused2_task = [&](int jb, int pin, int pout) {
        {
            const float4* h1p = (const float4*)g_h1[pin];
            const float4* h2p = (const float4*)g_h2[pin];
            float4* s4 = (float4*)sv;
            s4[tid]       = __ldcg(h1p + tid);
            s4[128 + tid] = __ldcg(h1p + 128 + tid);
            s4[256 + tid] = __ldcg(h2p + tid);
            s4[384 + tid] = __ldcg(h2p + 128 + tid);
            const float4* ev = (const float4*)(emb + (size_t)s_gidx * DW);
            s4[512 + tid] = ev[tid];
        }
        __syncthreads();
        const float4* hv = (const float4*)sv;

        #pragma unroll
        for (int half = 0; half < 2; half++) {
            const int j = jb + half * 512;
            const int r = warp * H + j;
            const int4* w1p = (const int4*)(g_whh1h + (size_t)r * H);
            const int4* w2p = (const int4*)(g_whh2h + (size_t)r * H);
            const int4* wep = (const int4*)(g_wih2h + (size_t)r * (H + DW) + H);
            int4 a1[4], a2[4], e2[2];
            #pragma unroll
            for (int u = 0; u < 4; u++) a1[u] = w1p[lane + 32 * u];
            #pragma unroll
            for (int u = 0; u < 4; u++) a2[u] = w2p[lane + 32 * u];
            #pragma unroll
            for (int u = 0; u < 2; u++) e2[u] = wep[lane + 32 * u];

            float s1 = 0.0f, s2 = 0.0f;
            #pragma unroll
            for (int u = 0; u < 4; u++) s1 += dot8h(a1[u], hv, (lane + 32 * u) * 2);
            #pragma unroll
            for (int u = 0; u < 4; u++) s2 += dot8h(a2[u], hv, H / 4 + (lane + 32 * u) * 2);
            #pragma unroll
            for (int u = 0; u < 2; u++) s2 += dot8h(e2[u], hv, 2 * H / 4 + (lane + 32 * u) * 2);
            #pragma unroll
            for (int o = 16; o; o >>= 1) {
                s1 += __shfl_xor_sync(0xffffffffu, s1, o);
                s2 += __shfl_xor_sync(0xffffffffu, s2, o);
            }
            if (lane == 0) {
                red[warp] = s1 + b_ih1[r] + b_hh1[r];
                g_p2[r]   = s2;
            }
            __syncthreads();
            if (tid == 0) {
                const float gi = red[0], gf = red[1], gg = red[2], go = red[3];
                const float cn = sigmoidf_(gf) * __ldcg(&g_c1[j]) + sigmoidf_(gi) * tanhf(gg);
                g_c1[j]       = cn;
                g_h1[pout][j] = sigmoidf_(go) * tanhf(cn);
                if (half == 1) { __threadfence(); atomicAdd(&g_h1cnt, 1u); }
            }
            __syncthreads();
        }
    };

    // -------- dependent 2-row consumer --------
    auto dep2_task = [&](int jb, int pout, int t) {
        if (tid == 0) {
            const unsigned target = 512u * (unsigned)(t + 1);
            while (*(volatile unsigned*)&g_h1cnt < target) __nanosleep(128);
            __threadfence();
        }
        __syncthreads();
        {
            const float4* h1p = (const float4*)g_h1[pout];
            float4* s4 = (float4*)sv;
            s4[tid]       = __ldcg(h1p + tid);
            s4[128 + tid] = __ldcg(h1p + 128 + tid);
        }
        __syncthreads();
        const float4* hv = (const float4*)sv;

        #pragma unroll
        for (int half = 0; half < 2; half++) {
            const int j = jb + half * 512;
            const int r = warp * H + j;
            const int4* wr = (const int4*)(g_wih2h + (size_t)r * (H + DW));
            int4 a[4];
            #pragma unroll
            for (int u = 0; u < 4; u++) a[u] = wr[lane + 32 * u];
            float s = 0.0f;
            #pragma unroll
            for (int u = 0; u < 4; u++) s += dot8h(a[u], hv, (lane + 32 * u) * 2);
            #pragma unroll
            for (int o = 16; o; o >>= 1) s += __shfl_xor_sync(0xffffffffu, s, o);
            if (lane == 0) red[warp] = s + __ldcg(&g_p2[r]) + b_ih2[r] + b_hh2[r];
            __syncthreads();
            if (tid == 0) {
                const float gi = red[0], gf = red[1], gg = red[2], go = red[3];
                const float cn = sigmoidf_(gf) * __ldcg(&g_c2[j]) + sigmoidf_(gi) * tanhf(gg);
                g_c2[j]       = cn;
                g_h2[pout][j] = sigmoidf_(go) * tanhf(cn);
            }
            __syncthreads();
        }
    };

    // -------- WARP-level 8-row logits task: no block syncs --------
    auto logits_wtask = [&](int s_step, int wt) {
        const int page = s_step & 1;
        const float hs = s_hscale;
        float* out_t = out + (size_t)s_step * VOCAB;
        const int r0 = wt * 8;

        // hoisted row base pointers (computed once)
        const int4* w0 = (const int4*)(g_wq + (size_t)(r0 + 0) * (H / 4));
        const int4* w1 = (const int4*)(g_wq + (size_t)(r0 + 1) * (H / 4));
        const int4* w2 = (const int4*)(g_wq + (size_t)(r0 + 2) * (H / 4));
        const int4* w3 = (const int4*)(g_wq + (size_t)(r0 + 3) * (H / 4));
        const int4* w4 = (const int4*)(g_wq + (size_t)(r0 + 4) * (H / 4));
        const int4* w5 = (const int4*)(g_wq + (size_t)(r0 + 5) * (H / 4));
        const int4* w6 = (const int4*)(g_wq + (size_t)(r0 + 6) * (H / 4));
        const int4* w7 = (const int4*)(g_wq + (size_t)(r0 + 7) * (H / 4));

        int acc[8];
        #pragma unroll
        for (int rr = 0; rr < 8; rr++) acc[rr] = 0;
        #pragma unroll
        for (int k0 = 0; k0 < 2; k0++) {
            const int k = lane + 32 * k0;
            const int4 h = qh4[k];
            int4 a;
            a = w0[k]; acc[0] = __dp4a(a.x, h.x, acc[0]); acc[0] = __dp4a(a.y, h.y, acc[0]);
                       acc[0] = __dp4a(a.z, h.z, acc[0]); acc[0] = __dp4a(a.w, h.w, acc[0]);
            a = w1[k]; acc[1] = __dp4a(a.x, h.x, acc[1]); acc[1] = __dp4a(a.y, h.y, acc[1]);
                       acc[1] = __dp4a(a.z, h.z, acc[1]); acc[1] = __dp4a(a.w, h.w, acc[1]);
            a = w2[k]; acc[2] = __dp4a(a.x, h.x, acc[2]); acc[2] = __dp4a(a.y, h.y, acc[2]);
                       acc[2] = __dp4a(a.z, h.z, acc[2]); acc[2] = __dp4a(a.w, h.w, acc[2]);
            a = w3[k]; acc[3] = __dp4a(a.x, h.x, acc[3]); acc[3] = __dp4a(a.y, h.y, acc[3]);
                       acc[3] = __dp4a(a.z, h.z, acc[3]); acc[3] = __dp4a(a.w, h.w, acc[3]);
            a = w4[k]; acc[4] = __dp4a(a.x, h.x, acc[4]); acc[4] = __dp4a(a.y, h.y, acc[4]);
                       acc[4] = __dp4a(a.z, h.z, acc[4]); acc[4] = __dp4a(a.w, h.w, acc[4]);
            a = w5[k]; acc[5] = __dp4a(a.x, h.x, acc[5]); acc[5] = __dp4a(a.y, h.y, acc[5]);
                       acc[5] = __dp4a(a.z, h.z, acc[5]); acc[5] = __dp4a(a.w, h.w, acc[5]);
            a = w6[k]; acc[6] = __dp4a(a.x, h.x, acc[6]); acc[6] = __dp4a(a.y, h.y, acc[6]);
                       acc[6] = __dp4a(a.z, h.z, acc[6]); acc[6] = __dp4a(a.w, h.w, acc[6]);
            a = w7[k]; acc[7] = __dp4a(a.x, h.x, acc[7]); acc[7] = __dp4a(a.y, h.y, acc[7]);
                       acc[7] = __dp4a(a.z, h.z, acc[7]); acc[7] = __dp4a(a.w, h.w, acc[7]);
        }
        #pragma unroll
        for (int rr = 0; rr < 8; rr++) acc[rr] = __reduce_add_sync(0xffffffffu, acc[rr]);

        // lanes 0..7 each finalize one row, then shuffle-merge the 8-row lse partial
        float v = 0.0f;
        if (lane < 8) {
            v = g_wscale[r0 + lane] * hs * (float)acc[lane] + b_out[r0 + lane];
            out_t[r0 + lane] = v;
        }
        float m = (lane < 8) ? v : -3.0e38f;
        #pragma unroll
        for (int o = 4; o; o >>= 1) m = fmaxf(m, __shfl_xor_sync(0xffffffffu, m, o));
        float e = (lane < 8) ? __expf(v - m) : 0.0f;
        #pragma unroll
        for (int o = 4; o; o >>= 1) e += __shfl_xor_sync(0xffffffffu, e, o);
        if (lane == 0) {
            g_lmax[page][wt] = m;
            g_lsum[page][wt] = e;
        }
    };

    auto combine_task = [&](int s_step) {
        const int page = s_step & 1;
        float m = -3.0e38f, sum = 0.0f;
        for (int k = tid; k < LG_WT; k += 128) {
            const float m2 = __ldcg(&g_lmax[page][k]);
            const float s2 = __ldcg(&g_lsum[page][k]);
            if (m2 > m) { sum = sum * __expf(m - m2) + s2; m = m2; }
            else        { sum += s2 * __expf(m2 - m); }
        }
        sm128[tid] = m; sa128[tid] = sum;
        __syncthreads();
        for (int off = 64; off; off >>= 1) {
            if (tid < off) {
                const float m1 = sm128[tid], sA = sa128[tid];
                const float m2 = sm128[tid + off], sB = sa128[tid + off];
                if (m2 > m1) { sm128[tid] = m2; sa128[tid] = sB + sA * __expf(m1 - m2); }
                else         { sa128[tid] = sA + sB * __expf(m2 - m1); }
            }
            __syncthreads();
        }
        if (tid == 0) g_norm[page] = sm128[0] + logf(sa128[0]);
        __syncthreads();
    };

    auto norm_task = [&](int s_step, int k) {
        const float n = __ldcg(&g_norm[s_step & 1]);
        float4* p = (float4*)(out + (size_t)s_step * VOCAB) + k * 1000;
        for (int i = tid; i < 1000; i += 128) {
            float4 v = __ldcg(p + i);
            v.x -= n; v.y -= n; v.z -= n; v.w -= n;
            p[i] = v;
        }
    };

    auto preamble = [&](int pin, int t) {
        const float4* h2p = (const float4*)g_h2[pin];
        const float4 va = __ldcg(h2p + tid);
        const float4 vb = __ldcg(h2p + 128 + tid);
        float am = fmaxf(fmaxf(fabsf(va.x), fabsf(va.y)), fmaxf(fabsf(va.z), fabsf(va.w)));
        am = fmaxf(am, fmaxf(fmaxf(fabsf(vb.x), fabsf(vb.y)), fmaxf(fabsf(vb.z), fabsf(vb.w))));
        float bm = va.x; int bi = 4 * tid;
        if (va.y > bm) { bm = va.y; bi = 4 * tid + 1; }
        if (va.z > bm) { bm = va.z; bi = 4 * tid + 2; }
        if (va.w > bm) { bm = va.w; bi = 4 * tid + 3; }
        if (vb.x > bm) { bm = vb.x; bi = 512 + 4 * tid; }
        if (vb.y > bm) { bm = vb.y; bi = 512 + 4 * tid + 1; }
        if (vb.z > bm) { bm = vb.z; bi = 512 + 4 * tid + 2; }
        if (vb.w > bm) { bm = vb.w; bi = 512 + 4 * tid + 3; }
        #pragma unroll
        for (int o = 16; o; o >>= 1) {
            const float v2 = __shfl_xor_sync(0xffffffffu, bm, o);
            const int   i2 = __shfl_xor_sync(0xffffffffu, bi, o);
            if (v2 > bm || (v2 == bm && i2 < bi)) { bm = v2; bi = i2; }
            am = fmaxf(am, __shfl_xor_sync(0xffffffffu, am, o));
        }
        if (lane == 0) { s_m[warp] = bm; s_i[warp] = bi; s_a[warp] = am; }
        __syncthreads();
        if (tid == 0) {
            float fm = s_m[0]; int fi = s_i[0];
            float fa = s_a[0];
            #pragma unroll
            for (int u = 1; u < 4; u++) {
                if (s_m[u] > fm || (s_m[u] == fm && s_i[u] < fi)) { fm = s_m[u]; fi = s_i[u]; }
                fa = fmaxf(fa, s_a[u]);
            }
            s_hscale = fa / 127.0f;
            s_inv    = (fa > 0.0f) ? 127.0f / fa : 0.0f;
            s_gidx   = (t == 0) ? 0 : fi;
        }
        __syncthreads();
        const float inv = s_inv;
        ((int*)qh4)[tid]       = pack4(va, inv);
        ((int*)qh4)[128 + tid] = pack4(vb, inv);
        __syncthreads();
    };

    // ================= main decode loop: role-based schedule, ONE barrier/step =============
    for (int t = 0; t < NSTEP; t++) {
        const int pin = t & 1, pout = 1 - pin;

        preamble(pin, t);

        // recurrence producers
        if (b < 512u) fused2_task((int)b, pin, pout);

        // warp-level logits for step t-1 (blocks [0,1000) => wgid < 4000)
        if (t >= 1 && wgid < LG_WT) logits_wtask(t - 1, wgid);

        // recurrence consumers (their warps did logits first; spin-wait is now hidden)
        if (b >= 512u && b < 1024u) dep2_task((int)b - 512, pout, t);

        // lse combine for step t-2 / norm for step t-3
        if (b == 1024u && t >= 2) combine_task(t - 2);
        if (b >= 1025u && b < 1025u + NORM_TASKS && t >= 3) norm_task(t - 3, (int)b - 1025);

        gbar(G);
    }

    // ================= drain =================
    preamble(NSTEP & 1, NSTEP);
    if (wgid < LG_WT) logits_wtask(NSTEP - 1, wgid);
    if (b == 1024u) combine_task(NSTEP - 2);
    if (b >= 1025u && b < 1025u + NORM_TASKS) norm_task(NSTEP - 3, (int)b - 1025);
    gbar(G);
    if (b == 1024u) combine_task(NSTEP - 1);
    if (b >= 1025u && b < 1025u + NORM_TASKS) norm_task(NSTEP - 2, (int)b - 1025);
    gbar(G);
    if (b >= 1025u && b < 1025u + NORM_TASKS) norm_task(NSTEP - 1, (int)b - 1025);
}

// ---------------- host driver ----------------
extern "C" void kernel_launch(void* const* d_in, const int* in_sizes, int n_in,
                              void* d_out, int out_size)
{
    const float* vid   = (const float*)d_in[0];
    const float* w_ih1 = (const float*)d_in[1];
    const float* w_hh1 = (const float*)d_in[2];
    const float* b_ih1 = (const float*)d_in[3];
    const float* b_hh1 = (const float*)d_in[4];
    const float* w_ih2 = (const float*)d_in[5];
    const float* w_hh2 = (const float*)d_in[6];
    const float* b_ih2 = (const float*)d_in[7];
    const float* b_hh2 = (const float*)d_in[8];
    const float* emb   = (const float*)d_in[9];
    const float* w_out = (const float*)d_in[10];
    const float* b_out = (const float*)d_in[11];
    float* out = (float*)d_out;

    (void)in_sizes; (void)n_in; (void)out_size;

    static cudaStream_t sB = nullptr;
    static cudaEvent_t evStart = nullptr, evB = nullptr;
    static int smCount = 0;
    if (!sB) {
        cudaStreamCreateWithFlags(&sB, cudaStreamNonBlocking);
        cudaEventCreateWithFlags(&evStart, cudaEventDisableTiming);
        cudaEventCreateWithFlags(&evB,     cudaEventDisableTiming);
        cudaDeviceGetAttribute(&smCount, cudaDevAttrMultiProcessorCount, 0);
    }
    const unsigned G = (unsigned)smCount * 8u;   // 1184 or 1216; divisible by 32

    cudaEventRecord(evStart, 0);
    cudaStreamWaitEvent(sB, evStart, 0);
    k_prep<<<3048, 256, 0, sB>>>(w_out, w_hh1, w_ih2, w_hh2);
    cudaEventRecord(evB, sB);

    k_lstm1_enc<<<H, 128>>>(w_ih1, vid, b_ih1, b_hh1);
    k_l2enc<<<H, 128>>>(w_ih2, b_ih2, b_hh2);

    cudaStreamWaitEvent(0, evB, 0);
    k_decode<<<G, 128>>>(b_ih1, b_hh1, b_ih2, b_hh2, emb, b_out, out, G);
}